// round 15
// baseline (speedup 1.0000x reference)
#include <cuda_runtime.h>
#include <cuda_bf16.h>
#include <cstdint>
#include <math.h>

#define BB   2
#define SS   1024
#define DMODEL 1024
#define NH   16
#define NLAYER 4
#define DFFN 4096
#define HDIM 64
#define NTOK (BB*SS)          // 2048
#define NREL (2*SS-1)         // 2047

// ---------------- static scratch ----------------
__device__ float          g_X  [NTOK*DMODEL];            // fp32 activations
__device__ __nv_bfloat16  g_Xs [NTOK*2*DMODEL];          // split of layer input
__device__ __nv_bfloat16  g_Qs [NTOK*2*DMODEL];
__device__ __nv_bfloat16  g_Ks [NTOK*2*DMODEL];          // split of K' = K/8 + Ebar
__device__ float          g_V  [NTOK*DMODEL];
__device__ __nv_bfloat16  g_VTs[(size_t)BB*NH*HDIM*2*SS];// per-head V^T split
__device__ __nv_bfloat16  g_AOs[NTOK*2*DMODEL];
__device__ float          g_T1 [NTOK*DMODEL];
__device__ float          g_X1 [NTOK*DMODEL];
__device__ __nv_bfloat16  g_X1s[NTOK*2*DMODEL];
__device__ __nv_bfloat16  g_Hs [(size_t)NTOK*2*DFFN];
__device__ float          g_EB [SS*HDIM];

// ---------------- helpers ----------------
__device__ __forceinline__ uint32_t smem_to_u32(const void* p) {
    uint32_t a;
    asm("{ .reg .u64 t; cvta.to.shared.u64 t, %1; cvt.u32.u64 %0, t; }" : "=r"(a) : "l"(p));
    return a;
}
__device__ __forceinline__ void cp_async16(uint32_t s, const void* g) {
    asm volatile("cp.async.cg.shared.global [%0], [%1], 16;" :: "r"(s), "l"(g) : "memory");
}
#define CP_COMMIT() asm volatile("cp.async.commit_group;" ::: "memory")
#define CP_WAIT(n)  asm volatile("cp.async.wait_group %0;" :: "n"(n) : "memory")

__device__ __forceinline__ void ldsm_x4(uint32_t addr, uint32_t& r0, uint32_t& r1,
                                        uint32_t& r2, uint32_t& r3) {
    asm volatile("ldmatrix.sync.aligned.m8n8.x4.shared.b16 {%0,%1,%2,%3}, [%4];"
                 : "=r"(r0), "=r"(r1), "=r"(r2), "=r"(r3) : "r"(addr));
}
__device__ __forceinline__ void mma16816(float* c, const uint32_t* a, uint32_t b0, uint32_t b1) {
    asm volatile(
        "mma.sync.aligned.m16n8k16.row.col.f32.bf16.bf16.f32 "
        "{%0,%1,%2,%3}, {%4,%5,%6,%7}, {%8,%9}, {%0,%1,%2,%3};"
        : "+f"(c[0]), "+f"(c[1]), "+f"(c[2]), "+f"(c[3])
        : "r"(a[0]), "r"(a[1]), "r"(a[2]), "r"(a[3]), "r"(b0), "r"(b1));
}

struct __align__(8) bh4 { __nv_bfloat16 h[4]; };
__device__ __forceinline__ void split2(float v, __nv_bfloat16& hi, __nv_bfloat16& lo) {
    hi = __float2bfloat16(v);
    lo = __float2bfloat16(v - __bfloat162float(hi));
}
__device__ __forceinline__ uint32_t packbf(float x, float y) {
    __nv_bfloat162 t; t.x = __float2bfloat16(x); t.y = __float2bfloat16(y);
    return *(uint32_t*)&t;
}

// =======================================================================
// Shared GEMM machinery (round-13 proven): 3-term split, in-kernel weight
// split. CTA 128 thr, 4 warps (2m x 2n), warp tile 64x32, block 128x64,
// 2-stage, 110.6 KB smem, 2 CTAs/SM.
// =======================================================================
#define GEMM_BODY_DECLS                                                     \
    extern __shared__ __align__(16) char smraw[];                           \
    constexpr int LDS = 72;                                                 \
    constexpr int ASZ = 128 * LDS * 2;                                      \
    constexpr int BSZ = 64 * LDS * 2;                                       \
    constexpr int STAGE = 2 * ASZ + 2 * BSZ;                                \
    const int tid = threadIdx.x;                                            \
    const int m0 = blockIdx.y * 128, n0 = blockIdx.x * 64;                  \
    const int lane = tid & 31, wid = tid >> 5;                              \
    const int warp_m = wid & 1, warp_n = wid >> 1;

template<int DUMMY>
struct GemmCore {};

// (machinery is expressed inline in each kernel to keep lambdas simple)

// ---------------- standard GEMM (O-proj, FFN1, FFN2) ----------------
// EPI: 0 f32+bias | 1 split+bias | 2 split+bias+gelu
template<int EPI>
__global__ void __launch_bounds__(128) mma_gemm(
    const __nv_bfloat16* __restrict__ A, long lda, long csA, long loA,
    const float* __restrict__ B, long ldb,
    const float* __restrict__ bias,
    void* __restrict__ Cv, long ldc, long loOff, int T)
{
    GEMM_BODY_DECLS

    auto loadA = [&](int buf, int i) {
        const uint32_t base = smem_to_u32(smraw + (long)buf * STAGE);
        const long colA = (long)i * csA;
        #pragma unroll
        for (int h = 0; h < 2; h++) {
            const long ca = colA + (h ? loA : 0);
            const uint32_t sa = base + h * ASZ;
            #pragma unroll
            for (int it = 0; it < 8; it++) {
                const int idx = tid + it * 128;
                const int row = idx >> 3, c = idx & 7;
                cp_async16(sa + row * (LDS * 2) + c * 16,
                           A + (long)(m0 + row) * lda + ca + c * 8);
            }
        }
        CP_COMMIT();
    };

    float breg[32];
    auto ldgB = [&](int i) {
        const long col = (long)i * 64;
        #pragma unroll
        for (int it = 0; it < 8; it++) {
            const int idx = tid + it * 128;
            const int row = idx >> 4, c = idx & 15;
            *(float4*)&breg[it * 4] =
                *(const float4*)&B[(long)(n0 + row) * ldb + col + c * 4];
        }
    };
    auto stsB = [&](int buf) {
        char* base = smraw + (long)buf * STAGE + 2 * ASZ;
        #pragma unroll
        for (int it = 0; it < 8; it++) {
            const int idx = tid + it * 128;
            const int row = idx >> 4, c = idx & 15;
            bh4 hi, lo;
            #pragma unroll
            for (int j = 0; j < 4; j++) split2(breg[it * 4 + j], hi.h[j], lo.h[j]);
            *(bh4*)(base + row * (LDS * 2) + c * 8)       = hi;
            *(bh4*)(base + BSZ + row * (LDS * 2) + c * 8) = lo;
        }
    };

    float acc[4][4][4];
    #pragma unroll
    for (int mi = 0; mi < 4; mi++)
        #pragma unroll
        for (int ni = 0; ni < 4; ni++)
            #pragma unroll
            for (int j = 0; j < 4; j++) acc[mi][ni][j] = 0.f;

    const int aRow = (lane & 7) + ((lane >> 3) & 1) * 8;
    const int aK   = (lane >> 4) * 8;
    const int bN   = ((lane >> 4) * 8) + (lane & 7);
    const int bK   = ((lane >> 3) & 1) * 8;

    auto compute_stage = [&](int buf) {
        const uint32_t base = smem_to_u32(smraw + (long)buf * STAGE);
        const uint32_t sAhi = base, sAlo = base + ASZ;
        const uint32_t sBhi = base + 2 * ASZ, sBlo = sBhi + BSZ;
        #pragma unroll
        for (int k16 = 0; k16 < 4; k16++) {
            const int ka = k16 * 16 + aK;
            const int kb = k16 * 16 + bK;
            uint32_t ah[4][4], al[4][4], bhf[2][4], blf[2][4];
            #pragma unroll
            for (int mi = 0; mi < 4; mi++) {
                const int m = warp_m * 64 + mi * 16 + aRow;
                ldsm_x4(sAhi + (m * LDS + ka) * 2, ah[mi][0], ah[mi][1], ah[mi][2], ah[mi][3]);
            }
            #pragma unroll
            for (int nb = 0; nb < 2; nb++) {
                const int n = warp_n * 32 + nb * 16 + bN;
                ldsm_x4(sBhi + (n * LDS + kb) * 2, bhf[nb][0], bhf[nb][1], bhf[nb][2], bhf[nb][3]);
            }
            #pragma unroll
            for (int mi = 0; mi < 4; mi++)
                #pragma unroll
                for (int ni = 0; ni < 4; ni++)
                    mma16816(acc[mi][ni], ah[mi], bhf[ni >> 1][(ni & 1) * 2], bhf[ni >> 1][(ni & 1) * 2 + 1]);
            #pragma unroll
            for (int mi = 0; mi < 4; mi++) {
                const int m = warp_m * 64 + mi * 16 + aRow;
                ldsm_x4(sAlo + (m * LDS + ka) * 2, al[mi][0], al[mi][1], al[mi][2], al[mi][3]);
            }
            #pragma unroll
            for (int mi = 0; mi < 4; mi++)
                #pragma unroll
                for (int ni = 0; ni < 4; ni++)
                    mma16816(acc[mi][ni], al[mi], bhf[ni >> 1][(ni & 1) * 2], bhf[ni >> 1][(ni & 1) * 2 + 1]);
            #pragma unroll
            for (int nb = 0; nb < 2; nb++) {
                const int n = warp_n * 32 + nb * 16 + bN;
                ldsm_x4(sBlo + (n * LDS + kb) * 2, blf[nb][0], blf[nb][1], blf[nb][2], blf[nb][3]);
            }
            #pragma unroll
            for (int mi = 0; mi < 4; mi++)
                #pragma unroll
                for (int ni = 0; ni < 4; ni++)
                    mma16816(acc[mi][ni], ah[mi], blf[ni >> 1][(ni & 1) * 2], blf[ni >> 1][(ni & 1) * 2 + 1]);
        }
    };

    ldgB(0);
    loadA(0, 0);
    stsB(0);
    if (T > 1) ldgB(1);

    for (int t = 0; t < T; t++) {
        if (t + 1 < T) { loadA((t + 1) & 1, t + 1); CP_WAIT(1); }
        else           { CP_WAIT(0); }
        __syncthreads();
        compute_stage(t & 1);
        if (t + 1 < T) {
            stsB((t + 1) & 1);
            if (t + 2 < T) ldgB(t + 2);
        }
        __syncthreads();
    }

    const int g = lane >> 2, tig = lane & 3;
    #pragma unroll
    for (int mi = 0; mi < 4; mi++) {
        #pragma unroll
        for (int ni = 0; ni < 4; ni++) {
            #pragma unroll
            for (int half = 0; half < 2; half++) {
                const int r = m0 + warp_m * 64 + mi * 16 + g + half * 8;
                const int c = n0 + warp_n * 32 + ni * 8 + tig * 2;
                float v0 = acc[mi][ni][half * 2 + 0];
                float v1 = acc[mi][ni][half * 2 + 1];
                if (bias) { v0 += bias[c]; v1 += bias[c + 1]; }
                if (EPI == 2) {
                    v0 = 0.5f * v0 * (1.0f + erff(v0 * 0.70710678118654752f));
                    v1 = 0.5f * v1 * (1.0f + erff(v1 * 0.70710678118654752f));
                }
                if (EPI == 0) {
                    float* C = (float*)Cv;
                    float2 o; o.x = v0; o.y = v1;
                    *(float2*)&C[(long)r * ldc + c] = o;
                } else {
                    __nv_bfloat16* Cs = (__nv_bfloat16*)Cv;
                    __nv_bfloat16 h0, l0, h1, l1;
                    split2(v0, h0, l0); split2(v1, h1, l1);
                    __nv_bfloat162 hp, lp;
                    hp.x = h0; hp.y = h1; lp.x = l0; lp.y = l1;
                    *(__nv_bfloat162*)&Cs[(long)r * ldc + c]         = hp;
                    *(__nv_bfloat162*)&Cs[(long)r * ldc + c + loOff] = lp;
                }
            }
        }
    }
}

// ---------------- batched QKV GEMM: z selects weight + epilogue ----------------
// z=0: Q -> split Qs; z=1: K -> K/8+Ebar -> split Ks; z=2: V -> f32 V.
__global__ void __launch_bounds__(128) mma_gemm_qkv(
    const __nv_bfloat16* __restrict__ A, long lda, long csA, long loA,
    const float* __restrict__ Bq, const float* __restrict__ Bk,
    const float* __restrict__ Bv, long ldb,
    const float* __restrict__ bqv, const float* __restrict__ bkv,
    const float* __restrict__ bvv,
    const float* __restrict__ EB,
    __nv_bfloat16* __restrict__ Qs, __nv_bfloat16* __restrict__ Ks,
    float* __restrict__ Vout, int T)
{
    GEMM_BODY_DECLS
    const int z = blockIdx.z;
    const float* B    = (z == 0) ? Bq  : (z == 1) ? Bk  : Bv;
    const float* bias = (z == 0) ? bqv : (z == 1) ? bkv : bvv;

    auto loadA = [&](int buf, int i) {
        const uint32_t base = smem_to_u32(smraw + (long)buf * STAGE);
        const long colA = (long)i * csA;
        #pragma unroll
        for (int h = 0; h < 2; h++) {
            const long ca = colA + (h ? loA : 0);
            const uint32_t sa = base + h * ASZ;
            #pragma unroll
            for (int it = 0; it < 8; it++) {
                const int idx = tid + it * 128;
                const int row = idx >> 3, c = idx & 7;
                cp_async16(sa + row * (LDS * 2) + c * 16,
                           A + (long)(m0 + row) * lda + ca + c * 8);
            }
        }
        CP_COMMIT();
    };

    float breg[32];
    auto ldgB = [&](int i) {
        const long col = (long)i * 64;
        #pragma unroll
        for (int it = 0; it < 8; it++) {
            const int idx = tid + it * 128;
            const int row = idx >> 4, c = idx & 15;
            *(float4*)&breg[it * 4] =
                *(const float4*)&B[(long)(n0 + row) * ldb + col + c * 4];
        }
    };
    auto stsB = [&](int buf) {
        char* base = smraw + (long)buf * STAGE + 2 * ASZ;
        #pragma unroll
        for (int it = 0; it < 8; it++) {
            const int idx = tid + it * 128;
            const int row = idx >> 4, c = idx & 15;
            bh4 hi, lo;
            #pragma unroll
            for (int j = 0; j < 4; j++) split2(breg[it * 4 + j], hi.h[j], lo.h[j]);
            *(bh4*)(base + row * (LDS * 2) + c * 8)       = hi;
            *(bh4*)(base + BSZ + row * (LDS * 2) + c * 8) = lo;
        }
    };

    float acc[4][4][4];
    #pragma unroll
    for (int mi = 0; mi < 4; mi++)
        #pragma unroll
        for (int ni = 0; ni < 4; ni++)
            #pragma unroll
            for (int j = 0; j < 4; j++) acc[mi][ni][j] = 0.f;

    const int aRow = (lane & 7) + ((lane >> 3) & 1) * 8;
    const int aK   = (lane >> 4) * 8;
    const int bN   = ((lane >> 4) * 8) + (lane & 7);
    const int bK   = ((lane >> 3) & 1) * 8;

    auto compute_stage = [&](int buf) {
        const uint32_t base = smem_to_u32(smraw + (long)buf * STAGE);
        const uint32_t sAhi = base, sAlo = base + ASZ;
        const uint32_t sBhi = base + 2 * ASZ, sBlo = sBhi + BSZ;
        #pragma unroll
        for (int k16 = 0; k16 < 4; k16++) {
            const int ka = k16 * 16 + aK;
            const int kb = k16 * 16 + bK;
            uint32_t ah[4][4], al[4][4], bhf[2][4], blf[2][4];
            #pragma unroll
            for (int mi = 0; mi < 4; mi++) {
                const int m = warp_m * 64 + mi * 16 + aRow;
                ldsm_x4(sAhi + (m * LDS + ka) * 2, ah[mi][0], ah[mi][1], ah[mi][2], ah[mi][3]);
            }
            #pragma unroll
            for (int nb = 0; nb < 2; nb++) {
                const int n = warp_n * 32 + nb * 16 + bN;
                ldsm_x4(sBhi + (n * LDS + kb) * 2, bhf[nb][0], bhf[nb][1], bhf[nb][2], bhf[nb][3]);
            }
            #pragma unroll
            for (int mi = 0; mi < 4; mi++)
                #pragma unroll
                for (int ni = 0; ni < 4; ni++)
                    mma16816(acc[mi][ni], ah[mi], bhf[ni >> 1][(ni & 1) * 2], bhf[ni >> 1][(ni & 1) * 2 + 1]);
            #pragma unroll
            for (int mi = 0; mi < 4; mi++) {
                const int m = warp_m * 64 + mi * 16 + aRow;
                ldsm_x4(sAlo + (m * LDS + ka) * 2, al[mi][0], al[mi][1], al[mi][2], al[mi][3]);
            }
            #pragma unroll
            for (int mi = 0; mi < 4; mi++)
                #pragma unroll
                for (int ni = 0; ni < 4; ni++)
                    mma16816(acc[mi][ni], al[mi], bhf[ni >> 1][(ni & 1) * 2], bhf[ni >> 1][(ni & 1) * 2 + 1]);
            #pragma unroll
            for (int nb = 0; nb < 2; nb++) {
                const int n = warp_n * 32 + nb * 16 + bN;
                ldsm_x4(sBlo + (n * LDS + kb) * 2, blf[nb][0], blf[nb][1], blf[nb][2], blf[nb][3]);
            }
            #pragma unroll
            for (int mi = 0; mi < 4; mi++)
                #pragma unroll
                for (int ni = 0; ni < 4; ni++)
                    mma16816(acc[mi][ni], ah[mi], blf[ni >> 1][(ni & 1) * 2], blf[ni >> 1][(ni & 1) * 2 + 1]);
        }
    };

    ldgB(0);
    loadA(0, 0);
    stsB(0);
    if (T > 1) ldgB(1);

    for (int t = 0; t < T; t++) {
        if (t + 1 < T) { loadA((t + 1) & 1, t + 1); CP_WAIT(1); }
        else           { CP_WAIT(0); }
        __syncthreads();
        compute_stage(t & 1);
        if (t + 1 < T) {
            stsB((t + 1) & 1);
            if (t + 2 < T) ldgB(t + 2);
        }
        __syncthreads();
    }

    const int g = lane >> 2, tig = lane & 3;
    #pragma unroll
    for (int mi = 0; mi < 4; mi++) {
        #pragma unroll
        for (int ni = 0; ni < 4; ni++) {
            #pragma unroll
            for (int half = 0; half < 2; half++) {
                const int r = m0 + warp_m * 64 + mi * 16 + g + half * 8;
                const int c = n0 + warp_n * 32 + ni * 8 + tig * 2;
                float v0 = acc[mi][ni][half * 2 + 0] + bias[c];
                float v1 = acc[mi][ni][half * 2 + 1] + bias[c + 1];
                if (z == 1) {
                    const int sr = (r & (SS - 1)) * HDIM;
                    v0 = v0 * 0.125f + EB[sr + (c & (HDIM - 1))];
                    v1 = v1 * 0.125f + EB[sr + ((c + 1) & (HDIM - 1))];
                }
                if (z == 2) {
                    float2 o; o.x = v0; o.y = v1;
                    *(float2*)&Vout[(long)r * DMODEL + c] = o;
                } else {
                    __nv_bfloat16* Cs = (z == 0) ? Qs : Ks;
                    __nv_bfloat16 h0, l0, h1, l1;
                    split2(v0, h0, l0); split2(v1, h1, l1);
                    __nv_bfloat162 hp, lp;
                    hp.x = h0; hp.y = h1; lp.x = l0; lp.y = l1;
                    *(__nv_bfloat162*)&Cs[(long)r * (2 * DMODEL) + c]          = hp;
                    *(__nv_bfloat162*)&Cs[(long)r * (2 * DMODEL) + c + DMODEL] = lp;
                }
            }
        }
    }
}

// =======================================================================
// Fused flash attention (round-11/13 proven, expf).
// =======================================================================
__global__ void __launch_bounds__(256) flash_kernel(
    const __nv_bfloat16* __restrict__ Qs,
    const __nv_bfloat16* __restrict__ Ks,
    const __nv_bfloat16* __restrict__ VTs,
    __nv_bfloat16* __restrict__ AOs)
{
    constexpr int LDS = 72;
    constexpr int LDV = 136;
    constexpr int QSZ = 128 * LDS * 2;
    constexpr int KSZ = 128 * LDS * 2;
    constexpr int VSZ = 64 * LDV * 2;
    constexpr int FST = 2 * QSZ;
    constexpr int STG = 2 * KSZ + 2 * VSZ;

    extern __shared__ __align__(16) char sm[];
    const uint32_t smb = smem_to_u32(sm);
    const int bh = blockIdx.x, b = bh >> 4, h = bh & 15;
    const int s0 = blockIdx.y * 128;
    const int tid = threadIdx.x, lane = tid & 31, wid = tid >> 5;

    const long qrow0 = (long)(b * SS + s0);
    {
        #pragma unroll
        for (int hf = 0; hf < 2; hf++) {
            const uint32_t sq = smb + hf * QSZ;
            const long colq = h * HDIM + (hf ? DMODEL : 0);
            #pragma unroll
            for (int it = 0; it < 4; it++) {
                const int idx = tid + it * 256;
                const int row = idx >> 3, c = idx & 7;
                cp_async16(sq + row * (LDS * 2) + c * 16,
                           Qs + (qrow0 + row) * (2 * DMODEL) + colq + c * 8);
            }
        }
        CP_COMMIT();
    }

    auto load_kv = [&](int buf, int jt) {
        const uint32_t base = smb + FST + buf * STG;
        const int j0 = jt * 128;
        #pragma unroll
        for (int hf = 0; hf < 2; hf++) {
            const uint32_t sk = base + hf * KSZ;
            const long colk = h * HDIM + (hf ? DMODEL : 0);
            #pragma unroll
            for (int it = 0; it < 4; it++) {
                const int idx = tid + it * 256;
                const int row = idx >> 3, c = idx & 7;
                cp_async16(sk + row * (LDS * 2) + c * 16,
                           Ks + ((long)(b * SS + j0 + row)) * (2 * DMODEL) + colk + c * 8);
            }
        }
        #pragma unroll
        for (int hf = 0; hf < 2; hf++) {
            const uint32_t sv = base + 2 * KSZ + hf * VSZ;
            const long colv = j0 + (hf ? SS : 0);
            #pragma unroll
            for (int it = 0; it < 4; it++) {
                const int idx = tid + it * 256;
                const int row = idx >> 4, c = idx & 15;
                cp_async16(sv + row * (LDV * 2) + c * 16,
                           VTs + ((long)(bh * HDIM + row)) * (2 * SS) + colv + c * 8);
            }
        }
        CP_COMMIT();
    };

    const int aRow = (lane & 7) + ((lane >> 3) & 1) * 8;
    const int aK   = (lane >> 4) * 8;
    const int bN   = ((lane >> 4) * 8) + (lane & 7);
    const int bK   = ((lane >> 3) & 1) * 8;
    const int mrow = wid * 16 + aRow;

    float oacc[8][4];
    #pragma unroll
    for (int n = 0; n < 8; n++)
        #pragma unroll
        for (int j = 0; j < 4; j++) oacc[n][j] = 0.f;
    float m0v = -INFINITY, m1v = -INFINITY, l0 = 0.f, l1 = 0.f;

    load_kv(0, 0);
    for (int jt = 0; jt < 8; jt++) {
        if (jt + 1 < 8) { load_kv((jt + 1) & 1, jt + 1); CP_WAIT(1); }
        else            { CP_WAIT(0); }
        __syncthreads();
        const uint32_t base = smb + FST + (jt & 1) * STG;
        const uint32_t sKhi = base, sKlo = base + KSZ;
        const uint32_t sVhi = base + 2 * KSZ, sVlo = sVhi + VSZ;
        const uint32_t sQhi = smb, sQlo = smb + QSZ;

        float sacc[16][4];
        #pragma unroll
        for (int n = 0; n < 16; n++)
            #pragma unroll
            for (int j = 0; j < 4; j++) sacc[n][j] = 0.f;

        #pragma unroll
        for (int k16 = 0; k16 < 4; k16++) {
            const int ka = k16 * 16 + aK;
            const int kb = k16 * 16 + bK;
            uint32_t qh[4], ql[4], kf[8][4];
            ldsm_x4(sQhi + (mrow * LDS + ka) * 2, qh[0], qh[1], qh[2], qh[3]);
            #pragma unroll
            for (int jn = 0; jn < 8; jn++) {
                const int n = jn * 16 + bN;
                ldsm_x4(sKhi + (n * LDS + kb) * 2, kf[jn][0], kf[jn][1], kf[jn][2], kf[jn][3]);
            }
            #pragma unroll
            for (int n = 0; n < 16; n++)
                mma16816(sacc[n], qh, kf[n >> 1][(n & 1) * 2], kf[n >> 1][(n & 1) * 2 + 1]);
            ldsm_x4(sQlo + (mrow * LDS + ka) * 2, ql[0], ql[1], ql[2], ql[3]);
            #pragma unroll
            for (int n = 0; n < 16; n++)
                mma16816(sacc[n], ql, kf[n >> 1][(n & 1) * 2], kf[n >> 1][(n & 1) * 2 + 1]);
            #pragma unroll
            for (int jn = 0; jn < 8; jn++) {
                const int n = jn * 16 + bN;
                ldsm_x4(sKlo + (n * LDS + kb) * 2, kf[jn][0], kf[jn][1], kf[jn][2], kf[jn][3]);
            }
            #pragma unroll
            for (int n = 0; n < 16; n++)
                mma16816(sacc[n], qh, kf[n >> 1][(n & 1) * 2], kf[n >> 1][(n & 1) * 2 + 1]);
        }

        float mx0 = -INFINITY, mx1 = -INFINITY;
        #pragma unroll
        for (int n = 0; n < 16; n++) {
            mx0 = fmaxf(mx0, fmaxf(sacc[n][0], sacc[n][1]));
            mx1 = fmaxf(mx1, fmaxf(sacc[n][2], sacc[n][3]));
        }
        mx0 = fmaxf(mx0, __shfl_xor_sync(0xffffffffu, mx0, 1));
        mx0 = fmaxf(mx0, __shfl_xor_sync(0xffffffffu, mx0, 2));
        mx1 = fmaxf(mx1, __shfl_xor_sync(0xffffffffu, mx1, 1));
        mx1 = fmaxf(mx1, __shfl_xor_sync(0xffffffffu, mx1, 2));
        const float mn0 = fmaxf(m0v, mx0), mn1 = fmaxf(m1v, mx1);
        const float al0 = expf(m0v - mn0), al1 = expf(m1v - mn1);
        m0v = mn0; m1v = mn1;
        float s0l = 0.f, s1l = 0.f;
        #pragma unroll
        for (int n = 0; n < 16; n++) {
            sacc[n][0] = expf(sacc[n][0] - mn0);
            sacc[n][1] = expf(sacc[n][1] - mn0);
            sacc[n][2] = expf(sacc[n][2] - mn1);
            sacc[n][3] = expf(sacc[n][3] - mn1);
            s0l += sacc[n][0] + sacc[n][1];
            s1l += sacc[n][2] + sacc[n][3];
        }
        s0l += __shfl_xor_sync(0xffffffffu, s0l, 1);
        s0l += __shfl_xor_sync(0xffffffffu, s0l, 2);
        s1l += __shfl_xor_sync(0xffffffffu, s1l, 1);
        s1l += __shfl_xor_sync(0xffffffffu, s1l, 2);
        l0 = l0 * al0 + s0l;
        l1 = l1 * al1 + s1l;
        #pragma unroll
        for (int n = 0; n < 8; n++) {
            oacc[n][0] *= al0; oacc[n][1] *= al0;
            oacc[n][2] *= al1; oacc[n][3] *= al1;
        }

        #pragma unroll
        for (int kj = 0; kj < 8; kj++) {
            const int t0 = kj * 2, t1 = kj * 2 + 1;
            uint32_t ahf[4], alf[4];
            {
                __nv_bfloat16 h0, l0b, h1, l1b;
                split2(sacc[t0][0], h0, l0b); split2(sacc[t0][1], h1, l1b);
                ahf[0] = packbf(__bfloat162float(h0), __bfloat162float(h1));
                alf[0] = packbf(__bfloat162float(l0b), __bfloat162float(l1b));
                split2(sacc[t0][2], h0, l0b); split2(sacc[t0][3], h1, l1b);
                ahf[1] = packbf(__bfloat162float(h0), __bfloat162float(h1));
                alf[1] = packbf(__bfloat162float(l0b), __bfloat162float(l1b));
                split2(sacc[t1][0], h0, l0b); split2(sacc[t1][1], h1, l1b);
                ahf[2] = packbf(__bfloat162float(h0), __bfloat162float(h1));
                alf[2] = packbf(__bfloat162float(l0b), __bfloat162float(l1b));
                split2(sacc[t1][2], h0, l0b); split2(sacc[t1][3], h1, l1b);
                ahf[3] = packbf(__bfloat162float(h0), __bfloat162float(h1));
                alf[3] = packbf(__bfloat162float(l0b), __bfloat162float(l1b));
            }
            const int kb2 = kj * 16 + bK;
            uint32_t vf[4][4];
            #pragma unroll
            for (int nb = 0; nb < 4; nb++) {
                const int n = nb * 16 + bN;
                ldsm_x4(sVhi + (n * LDV + kb2) * 2, vf[nb][0], vf[nb][1], vf[nb][2], vf[nb][3]);
            }
            #pragma unroll
            for (int n = 0; n < 8; n++)
                mma16816(oacc[n], ahf, vf[n >> 1][(n & 1) * 2], vf[n >> 1][(n & 1) * 2 + 1]);
            #pragma unroll
            for (int n = 0; n < 8; n++)
                mma16816(oacc[n], alf, vf[n >> 1][(n & 1) * 2], vf[n >> 1][(n & 1) * 2 + 1]);
            #pragma unroll
            for (int nb = 0; nb < 4; nb++) {
                const int n = nb * 16 + bN;
                ldsm_x4(sVlo + (n * LDV + kb2) * 2, vf[nb][0], vf[nb][1], vf[nb][2], vf[nb][3]);
            }
            #pragma unroll
            for (int n = 0; n < 8; n++)
                mma16816(oacc[n], ahf, vf[n >> 1][(n & 1) * 2], vf[n >> 1][(n & 1) * 2 + 1]);
        }
        __syncthreads();
    }

    const int g = lane >> 2, tig = lane & 3;
    const float inv0 = 1.0f / l0, inv1 = 1.0f / l1;
    #pragma unroll
    for (int n = 0; n < 8; n++) {
        const int d = n * 8 + tig * 2;
        #pragma unroll
        for (int half = 0; half < 2; half++) {
            const long r = qrow0 + wid * 16 + g + half * 8;
            const float inv = half ? inv1 : inv0;
            const float v0 = oacc[n][half * 2 + 0] * inv;
            const float v1 = oacc[n][half * 2 + 1] * inv;
            __nv_bfloat16 h0, lo0, h1, lo1;
            split2(v0, h0, lo0); split2(v1, h1, lo1);
            __nv_bfloat162 hp, lp;
            hp.x = h0; hp.y = h1; lp.x = lo0; lp.y = lo1;
            __nv_bfloat16* dst = AOs + r * (2 * DMODEL) + h * HDIM + d;
            *(__nv_bfloat162*)dst            = hp;
            *(__nv_bfloat162*)(dst + DMODEL) = lp;
        }
    }
}

// ---------------- reductions ----------------
__device__ __forceinline__ float block_reduce_sum(float v, float* sh) {
    #pragma unroll
    for (int o = 16; o; o >>= 1) v += __shfl_xor_sync(0xffffffffu, v, o);
    int warp = threadIdx.x >> 5, lane = threadIdx.x & 31;
    if (lane == 0) sh[warp] = v;
    __syncthreads();
    if (threadIdx.x < 8) {
        float x = sh[threadIdx.x];
        #pragma unroll
        for (int o = 4; o; o >>= 1) x += __shfl_xor_sync(0xffu, x, o);
        if (threadIdx.x == 0) sh[0] = x;
    }
    __syncthreads();
    float r = sh[0];
    __syncthreads();
    return r;
}

// ---------------- Ebar ----------------
__global__ void ebar_kernel(const float* __restrict__ rel) {
    const int j = blockIdx.x, d = threadIdx.x;
    const float* r0 = rel + (long)(SS - 1 - j) * HDIM + d;
    float s = 0.f;
    #pragma unroll 4
    for (int k = 0; k < SS; k++) s += r0[(long)k * HDIM];
    g_EB[j * HDIM + d] = s * (1.0f / SS);
}

// ---------------- split fp32 [R,K] -> bf16 [R, 2K] (initial x only) ----------------
__global__ void __launch_bounds__(256) split_kernel(
    const float* __restrict__ in, __nv_bfloat16* __restrict__ out, long n, int kshift)
{
    const long i4 = ((long)blockIdx.x * 256 + threadIdx.x) * 4;
    if (i4 >= n) return;
    const long row = i4 >> kshift;
    const int  K   = 1 << kshift;
    const int  col = (int)(i4 & (K - 1));
    const float4 v = *(const float4*)&in[i4];
    bh4 hi, lo;
    split2(v.x, hi.h[0], lo.h[0]); split2(v.y, hi.h[1], lo.h[1]);
    split2(v.z, hi.h[2], lo.h[2]); split2(v.w, hi.h[3], lo.h[3]);
    *(bh4*)&out[row * 2 * K + col]     = hi;
    *(bh4*)&out[row * 2 * K + K + col] = lo;
}

// ---------------- V -> per-head V^T split ----------------
__global__ void split_transpose_v(const float* __restrict__ V, __nv_bfloat16* __restrict__ VT) {
    __shared__ float t[32][33];
    const int bh = blockIdx.z, b = bh >> 4, h = bh & 15;
    const int s0 = blockIdx.x * 32, d0 = blockIdx.y * 32;
    const int tx = threadIdx.x, ty = threadIdx.y;
    #pragma unroll
    for (int r = 0; r < 4; r++) {
        const int s = s0 + ty + r * 8;
        t[ty + r * 8][tx] = V[((long)b * SS + s) * DMODEL + h * HDIM + d0 + tx];
    }
    __syncthreads();
    #pragma unroll
    for (int r = 0; r < 4; r++) {
        const int d = d0 + ty + r * 8;
        const int s = s0 + tx;
        const float v = t[tx][ty + r * 8];
        __nv_bfloat16 hi, lo; split2(v, hi, lo);
        VT[((long)bh * HDIM + d) * (2 * SS) + s]      = hi;
        VT[((long)bh * HDIM + d) * (2 * SS) + SS + s] = lo;
    }
}

// ---------------- LN(xin + add) -> fp32 out + split out ----------------
__global__ void __launch_bounds__(256) ln_kernel(
    const float* __restrict__ xin, const float* __restrict__ add,
    const float* __restrict__ g, const float* __restrict__ be,
    float* __restrict__ out, __nv_bfloat16* __restrict__ outs)
{
    __shared__ float sh[8];
    const long row = blockIdx.x;
    const int t = threadIdx.x;
    const float4 a  = *(const float4*)&xin[row * DMODEL + t * 4];
    const float4 b2 = *(const float4*)&add[row * DMODEL + t * 4];
    float y[4] = {a.x + b2.x, a.y + b2.y, a.z + b2.z, a.w + b2.w};
    float s = y[0] + y[1] + y[2] + y[3];
    s = block_reduce_sum(s, sh);
    const float mean = s * (1.0f / DMODEL);
    float q = 0.f;
    #pragma unroll
    for (int i = 0; i < 4; i++) { const float d = y[i] - mean; q += d * d; }
    q = block_reduce_sum(q, sh);
    const float rstd = rsqrtf(q * (1.0f / DMODEL) + 1e-5f);
    const float4 gg = *(const float4*)&g[t * 4];
    const float4 bb = *(const float4*)&be[t * 4];
    float o[4];
    o[0] = (y[0] - mean) * rstd * gg.x + bb.x;
    o[1] = (y[1] - mean) * rstd * gg.y + bb.y;
    o[2] = (y[2] - mean) * rstd * gg.z + bb.z;
    o[3] = (y[3] - mean) * rstd * gg.w + bb.w;
    *(float4*)&out[row * DMODEL + t * 4] = *(float4*)o;
    bh4 hi, lo;
    #pragma unroll
    for (int i = 0; i < 4; i++) split2(o[i], hi.h[i], lo.h[i]);
    *(bh4*)&outs[row * 2 * DMODEL + t * 4]          = hi;
    *(bh4*)&outs[row * 2 * DMODEL + DMODEL + t * 4] = lo;
}

// ---------------- host ----------------
extern "C" void kernel_launch(void* const* d_in, const int* in_sizes, int n_in,
                              void* d_out, int out_size)
{
    (void)in_sizes; (void)n_in; (void)out_size;
    const float* x   = (const float*)d_in[0];
    const float* Wq  = (const float*)d_in[1];
    const float* bq  = (const float*)d_in[2];
    const float* Wk  = (const float*)d_in[3];
    const float* bk  = (const float*)d_in[4];
    const float* Wv  = (const float*)d_in[5];
    const float* bv  = (const float*)d_in[6];
    const float* Wo  = (const float*)d_in[7];
    const float* bo  = (const float*)d_in[8];
    const float* rel = (const float*)d_in[9];
    const float* W1  = (const float*)d_in[10];
    const float* b1  = (const float*)d_in[11];
    const float* W2  = (const float*)d_in[12];
    const float* b2  = (const float*)d_in[13];
    const float* g1  = (const float*)d_in[14];
    const float* be1 = (const float*)d_in[15];
    const float* g2  = (const float*)d_in[16];
    const float* be2 = (const float*)d_in[17];
    float* out = (float*)d_out;

    float *pX, *pV, *pT1, *pX1, *pEB;
    __nv_bfloat16 *pXs, *pQs, *pKs, *pVTs, *pAOs, *pX1s, *pHs;
    cudaGetSymbolAddress((void**)&pX,   g_X);
    cudaGetSymbolAddress((void**)&pXs,  g_Xs);
    cudaGetSymbolAddress((void**)&pQs,  g_Qs);
    cudaGetSymbolAddress((void**)&pKs,  g_Ks);
    cudaGetSymbolAddress((void**)&pV,   g_V);
    cudaGetSymbolAddress((void**)&pVTs, g_VTs);
    cudaGetSymbolAddress((void**)&pAOs, g_AOs);
    cudaGetSymbolAddress((void**)&pT1,  g_T1);
    cudaGetSymbolAddress((void**)&pX1,  g_X1);
    cudaGetSymbolAddress((void**)&pX1s, g_X1s);
    cudaGetSymbolAddress((void**)&pHs,  g_Hs);
    cudaGetSymbolAddress((void**)&pEB,  g_EB);

    constexpr int LDS = 72;
    const int SMEM  = 2 * (2 * 128 * LDS * 2 + 2 * 64 * LDS * 2);  // 110592
    const int FSMEM = 2 * (128 * LDS * 2) + 2 * (2 * 128 * LDS * 2 + 2 * 64 * 136 * 2); // 180224
    cudaFuncSetAttribute((void*)mma_gemm<0>,   cudaFuncAttributeMaxDynamicSharedMemorySize, SMEM);
    cudaFuncSetAttribute((void*)mma_gemm<1>,   cudaFuncAttributeMaxDynamicSharedMemorySize, SMEM);
    cudaFuncSetAttribute((void*)mma_gemm<2>,   cudaFuncAttributeMaxDynamicSharedMemorySize, SMEM);
    cudaFuncSetAttribute((void*)mma_gemm_qkv,  cudaFuncAttributeMaxDynamicSharedMemorySize, SMEM);
    cudaFuncSetAttribute((void*)flash_kernel,  cudaFuncAttributeMaxDynamicSharedMemorySize, FSMEM);

    const dim3 blk(256);
    const dim3 blkG(128);

    split_kernel<<<(NTOK * DMODEL) / 1024, blk>>>(x, pXs, (long)NTOK * DMODEL, 10);

    for (int l = 0; l < NLAYER; l++) {
        const float* xin  = (l == 0) ? x : pX;
        const float* Wq_l = Wq + (long)l * DMODEL * DMODEL;
        const float* Wk_l = Wk + (long)l * DMODEL * DMODEL;
        const float* Wv_l = Wv + (long)l * DMODEL * DMODEL;
        const float* Wo_l = Wo + (long)l * DMODEL * DMODEL;
        const float* W1_l = W1 + (long)l * DFFN * DMODEL;
        const float* W2_l = W2 + (long)l * DMODEL * DFFN;
        const float* bq_l = bq + (long)l * DMODEL;
        const float* bk_l = bk + (long)l * DMODEL;
        const float* bv_l = bv + (long)l * DMODEL;
        const float* bo_l = bo + (long)l * DMODEL;
        const float* b1_l = b1 + (long)l * DFFN;
        const float* b2_l = b2 + (long)l * DMODEL;
        const float* g1_l = g1 + (long)l * DMODEL;
        const float* be1_l= be1+ (long)l * DMODEL;
        const float* g2_l = g2 + (long)l * DMODEL;
        const float* be2_l= be2+ (long)l * DMODEL;
        const float* rel_l= rel+ (long)l * NREL * HDIM;

        ebar_kernel<<<SS, HDIM>>>(rel_l);

        // Q,K',V projections batched in one launch (z = 0/1/2; 768 CTAs)
        mma_gemm_qkv<<<dim3(16,16,3), blkG, SMEM>>>(
            pXs, 2*DMODEL, 64, DMODEL,
            Wq_l, Wk_l, Wv_l, DMODEL,
            bq_l, bk_l, bv_l, pEB,
            pQs, pKs, pV, 16);
        split_transpose_v<<<dim3(SS/32, HDIM/32, BB*NH), dim3(32,8)>>>(pV, pVTs);

        // fused attention: QK' -> softmax -> PV -> split AO
        flash_kernel<<<dim3(BB*NH, SS/128), blk, FSMEM>>>(pQs, pKs, pVTs, pAOs);

        // output projection -> fp32 T1
        mma_gemm<0><<<dim3(16,16,1), blkG, SMEM>>>(
            pAOs, 2*DMODEL, 64, DMODEL, Wo_l, DMODEL, bo_l,
            pT1, DMODEL, 0, 16);

        ln_kernel<<<NTOK, blk>>>(xin, pT1, g1_l, be1_l, pX1, pX1s);

        // FFN1 (gelu) -> split Hs
        mma_gemm<2><<<dim3(64,16,1), blkG, SMEM>>>(
            pX1s, 2*DMODEL, 64, DMODEL, W1_l, DMODEL, b1_l,
            pHs, 2*DFFN, DFFN, 16);

        // FFN2 -> fp32 T1
        mma_gemm<0><<<dim3(16,16,1), blkG, SMEM>>>(
            pHs, 2*DFFN, 64, DFFN, W2_l, DFFN, b2_l,
            pT1, DMODEL, 0, 64);

        ln_kernel<<<NTOK, blk>>>(pX1, pT1, g2_l, be2_l, (l == NLAYER-1) ? out : pX, pXs);
    }
}

// round 16
// speedup vs baseline: 1.0225x; 1.0225x over previous
#include <cuda_runtime.h>
#include <cuda_bf16.h>
#include <cstdint>
#include <math.h>

#define BB   2
#define SS   1024
#define DMODEL 1024
#define NH   16
#define NLAYER 4
#define DFFN 4096
#define HDIM 64
#define NTOK (BB*SS)          // 2048
#define NREL (2*SS-1)         // 2047

// ---------------- static scratch ----------------
__device__ float          g_X  [NTOK*DMODEL];            // fp32 activations
__device__ __nv_bfloat16  g_Xs [NTOK*2*DMODEL];          // split of layer input
__device__ __nv_bfloat16  g_Qs [NTOK*2*DMODEL];
__device__ __nv_bfloat16  g_Ks [NTOK*2*DMODEL];          // split of K' = K/8 + Ebar
__device__ __nv_bfloat16  g_VTs[(size_t)BB*NH*HDIM*2*SS];// per-head V^T split
__device__ __nv_bfloat16  g_AOs[NTOK*2*DMODEL];
__device__ float          g_T1 [NTOK*DMODEL];
__device__ float          g_X1 [NTOK*DMODEL];
__device__ __nv_bfloat16  g_X1s[NTOK*2*DMODEL];
__device__ __nv_bfloat16  g_Hs [(size_t)NTOK*2*DFFN];
__device__ float          g_EB [SS*HDIM];

// ---------------- helpers ----------------
__device__ __forceinline__ uint32_t smem_to_u32(const void* p) {
    uint32_t a;
    asm("{ .reg .u64 t; cvta.to.shared.u64 t, %1; cvt.u32.u64 %0, t; }" : "=r"(a) : "l"(p));
    return a;
}
__device__ __forceinline__ void cp_async16(uint32_t s, const void* g) {
    asm volatile("cp.async.cg.shared.global [%0], [%1], 16;" :: "r"(s), "l"(g) : "memory");
}
#define CP_COMMIT() asm volatile("cp.async.commit_group;" ::: "memory")
#define CP_WAIT(n)  asm volatile("cp.async.wait_group %0;" :: "n"(n) : "memory")

__device__ __forceinline__ void ldsm_x4(uint32_t addr, uint32_t& r0, uint32_t& r1,
                                        uint32_t& r2, uint32_t& r3) {
    asm volatile("ldmatrix.sync.aligned.m8n8.x4.shared.b16 {%0,%1,%2,%3}, [%4];"
                 : "=r"(r0), "=r"(r1), "=r"(r2), "=r"(r3) : "r"(addr));
}
__device__ __forceinline__ void mma16816(float* c, const uint32_t* a, uint32_t b0, uint32_t b1) {
    asm volatile(
        "mma.sync.aligned.m16n8k16.row.col.f32.bf16.bf16.f32 "
        "{%0,%1,%2,%3}, {%4,%5,%6,%7}, {%8,%9}, {%0,%1,%2,%3};"
        : "+f"(c[0]), "+f"(c[1]), "+f"(c[2]), "+f"(c[3])
        : "r"(a[0]), "r"(a[1]), "r"(a[2]), "r"(a[3]), "r"(b0), "r"(b1));
}

struct __align__(8) bh4 { __nv_bfloat16 h[4]; };
__device__ __forceinline__ void split2(float v, __nv_bfloat16& hi, __nv_bfloat16& lo) {
    hi = __float2bfloat16(v);
    lo = __float2bfloat16(v - __bfloat162float(hi));
}
__device__ __forceinline__ uint32_t packbf(float x, float y) {
    __nv_bfloat162 t; t.x = __float2bfloat16(x); t.y = __float2bfloat16(y);
    return *(uint32_t*)&t;
}

// =======================================================================
// HMMA split-fp32 GEMM with IN-KERNEL weight splitting (round-13 proven).
// A: split bf16 [hi|lo] rows via cp.async; B: raw fp32 weights, reg-staged
// LDG.128 -> split2 -> Bhi/Blo smem. CTA 128 thr, 4 warps (2m x 2n),
// warp tile 64x32, block 128x64, 2-stage, 110.6 KB smem, 2 CTAs/SM.
// EPI: 0 f32+bias | 1 split+bias | 2 split+bias+gelu | 3 split+bias+kadjust
//      4 V-mode: bias, split, per-head TRANSPOSED store into VTs
//                (smem-staged -> coalesced; deletes split_transpose_v)
// =======================================================================
template<int EPI>
__global__ void __launch_bounds__(128) mma_gemm(
    const __nv_bfloat16* __restrict__ A, long lda, long csA, long loA,
    const float* __restrict__ B, long ldb,
    const float* __restrict__ bias, const float* __restrict__ EB,
    void* __restrict__ Cv, long ldc, long loOff, int T)
{
    extern __shared__ __align__(16) char smraw[];
    constexpr int LDS = 72;
    constexpr int ASZ = 128 * LDS * 2;
    constexpr int BSZ = 64 * LDS * 2;
    constexpr int STAGE = 2 * ASZ + 2 * BSZ;

    const int tid = threadIdx.x;
    const int m0 = blockIdx.y * 128, n0 = blockIdx.x * 64;
    const int lane = tid & 31, wid = tid >> 5;
    const int warp_m = wid & 1, warp_n = wid >> 1;

    auto loadA = [&](int buf, int i) {
        const uint32_t base = smem_to_u32(smraw + (long)buf * STAGE);
        const long colA = (long)i * csA;
        #pragma unroll
        for (int h = 0; h < 2; h++) {
            const long ca = colA + (h ? loA : 0);
            const uint32_t sa = base + h * ASZ;
            #pragma unroll
            for (int it = 0; it < 8; it++) {
                const int idx = tid + it * 128;
                const int row = idx >> 3, c = idx & 7;
                cp_async16(sa + row * (LDS * 2) + c * 16,
                           A + (long)(m0 + row) * lda + ca + c * 8);
            }
        }
        CP_COMMIT();
    };

    float breg[32];
    auto ldgB = [&](int i) {
        const long col = (long)i * 64;
        #pragma unroll
        for (int it = 0; it < 8; it++) {
            const int idx = tid + it * 128;
            const int row = idx >> 4, c = idx & 15;
            *(float4*)&breg[it * 4] =
                *(const float4*)&B[(long)(n0 + row) * ldb + col + c * 4];
        }
    };
    auto stsB = [&](int buf) {
        char* base = smraw + (long)buf * STAGE + 2 * ASZ;
        #pragma unroll
        for (int it = 0; it < 8; it++) {
            const int idx = tid + it * 128;
            const int row = idx >> 4, c = idx & 15;
            bh4 hi, lo;
            #pragma unroll
            for (int j = 0; j < 4; j++) split2(breg[it * 4 + j], hi.h[j], lo.h[j]);
            *(bh4*)(base + row * (LDS * 2) + c * 8)       = hi;
            *(bh4*)(base + BSZ + row * (LDS * 2) + c * 8) = lo;
        }
    };

    float acc[4][4][4];
    #pragma unroll
    for (int mi = 0; mi < 4; mi++)
        #pragma unroll
        for (int ni = 0; ni < 4; ni++)
            #pragma unroll
            for (int j = 0; j < 4; j++) acc[mi][ni][j] = 0.f;

    const int aRow = (lane & 7) + ((lane >> 3) & 1) * 8;
    const int aK   = (lane >> 4) * 8;
    const int bN   = ((lane >> 4) * 8) + (lane & 7);
    const int bK   = ((lane >> 3) & 1) * 8;

    auto compute_stage = [&](int buf) {
        const uint32_t base = smem_to_u32(smraw + (long)buf * STAGE);
        const uint32_t sAhi = base, sAlo = base + ASZ;
        const uint32_t sBhi = base + 2 * ASZ, sBlo = sBhi + BSZ;
        #pragma unroll
        for (int k16 = 0; k16 < 4; k16++) {
            const int ka = k16 * 16 + aK;
            const int kb = k16 * 16 + bK;
            uint32_t ah[4][4], al[4][4], bhf[2][4], blf[2][4];
            #pragma unroll
            for (int mi = 0; mi < 4; mi++) {
                const int m = warp_m * 64 + mi * 16 + aRow;
                ldsm_x4(sAhi + (m * LDS + ka) * 2, ah[mi][0], ah[mi][1], ah[mi][2], ah[mi][3]);
            }
            #pragma unroll
            for (int nb = 0; nb < 2; nb++) {
                const int n = warp_n * 32 + nb * 16 + bN;
                ldsm_x4(sBhi + (n * LDS + kb) * 2, bhf[nb][0], bhf[nb][1], bhf[nb][2], bhf[nb][3]);
            }
            #pragma unroll
            for (int mi = 0; mi < 4; mi++)
                #pragma unroll
                for (int ni = 0; ni < 4; ni++)
                    mma16816(acc[mi][ni], ah[mi], bhf[ni >> 1][(ni & 1) * 2], bhf[ni >> 1][(ni & 1) * 2 + 1]);
            #pragma unroll
            for (int mi = 0; mi < 4; mi++) {
                const int m = warp_m * 64 + mi * 16 + aRow;
                ldsm_x4(sAlo + (m * LDS + ka) * 2, al[mi][0], al[mi][1], al[mi][2], al[mi][3]);
            }
            #pragma unroll
            for (int mi = 0; mi < 4; mi++)
                #pragma unroll
                for (int ni = 0; ni < 4; ni++)
                    mma16816(acc[mi][ni], al[mi], bhf[ni >> 1][(ni & 1) * 2], bhf[ni >> 1][(ni & 1) * 2 + 1]);
            #pragma unroll
            for (int nb = 0; nb < 2; nb++) {
                const int n = warp_n * 32 + nb * 16 + bN;
                ldsm_x4(sBlo + (n * LDS + kb) * 2, blf[nb][0], blf[nb][1], blf[nb][2], blf[nb][3]);
            }
            #pragma unroll
            for (int mi = 0; mi < 4; mi++)
                #pragma unroll
                for (int ni = 0; ni < 4; ni++)
                    mma16816(acc[mi][ni], ah[mi], blf[ni >> 1][(ni & 1) * 2], blf[ni >> 1][(ni & 1) * 2 + 1]);
        }
    };

    ldgB(0);
    loadA(0, 0);
    stsB(0);
    if (T > 1) ldgB(1);

    for (int t = 0; t < T; t++) {
        if (t + 1 < T) { loadA((t + 1) & 1, t + 1); CP_WAIT(1); }
        else           { CP_WAIT(0); }
        __syncthreads();
        compute_stage(t & 1);
        if (t + 1 < T) {
            stsB((t + 1) & 1);
            if (t + 2 < T) ldgB(t + 2);
        }
        __syncthreads();
    }

    const int g = lane >> 2, tig = lane & 3;

    if (EPI == 4) {
        // ---- V-mode: split + transpose via smem, coalesced store to VTs ----
        __nv_bfloat16* sth = (__nv_bfloat16*)smraw;          // [64 d][136 s] hi
        __nv_bfloat16* stl = sth + 64 * 136;                 // lo
        #pragma unroll
        for (int mi = 0; mi < 4; mi++)
            #pragma unroll
            for (int ni = 0; ni < 4; ni++)
                #pragma unroll
                for (int half = 0; half < 2; half++) {
                    const int rl = warp_m * 64 + mi * 16 + g + half * 8;   // token in tile
                    const int cl = warp_n * 32 + ni * 8 + tig * 2;          // dim in head
                    float v0 = acc[mi][ni][half * 2 + 0] + bias[n0 + cl];
                    float v1 = acc[mi][ni][half * 2 + 1] + bias[n0 + cl + 1];
                    __nv_bfloat16 h0, l0, h1, l1;
                    split2(v0, h0, l0); split2(v1, h1, l1);
                    sth[cl * 136 + rl] = h0;       stl[cl * 136 + rl] = l0;
                    sth[(cl + 1) * 136 + rl] = h1; stl[(cl + 1) * 136 + rl] = l1;
                }
        __syncthreads();
        const int b     = m0 >> 10;
        const int sbase = m0 & 1023;
        const int bh    = b * NH + (n0 >> 6);
        __nv_bfloat16* VT = (__nv_bfloat16*)Cv;
        #pragma unroll
        for (int it = 0; it < 16; it++) {
            const int idx = tid + it * 128;      // 0..2047
            const int d   = idx >> 5;            // 0..63
            const int cs  = (idx & 31) * 4;      // 0..124
            bh4 vh = *(bh4*)&sth[d * 136 + cs];
            bh4 vl = *(bh4*)&stl[d * 136 + cs];
            const long base = ((long)bh * HDIM + d) * (2 * SS) + sbase + cs;
            *(bh4*)&VT[base]      = vh;
            *(bh4*)&VT[base + SS] = vl;
        }
    } else {
        #pragma unroll
        for (int mi = 0; mi < 4; mi++) {
            #pragma unroll
            for (int ni = 0; ni < 4; ni++) {
                #pragma unroll
                for (int half = 0; half < 2; half++) {
                    const int r = m0 + warp_m * 64 + mi * 16 + g + half * 8;
                    const int c = n0 + warp_n * 32 + ni * 8 + tig * 2;
                    float v0 = acc[mi][ni][half * 2 + 0];
                    float v1 = acc[mi][ni][half * 2 + 1];
                    if (bias) { v0 += bias[c]; v1 += bias[c + 1]; }
                    if (EPI == 3) {
                        const int sr = (r & (SS - 1)) * HDIM;
                        v0 = v0 * 0.125f + EB[sr + (c & (HDIM - 1))];
                        v1 = v1 * 0.125f + EB[sr + ((c + 1) & (HDIM - 1))];
                    }
                    if (EPI == 2) {
                        v0 = 0.5f * v0 * (1.0f + erff(v0 * 0.70710678118654752f));
                        v1 = 0.5f * v1 * (1.0f + erff(v1 * 0.70710678118654752f));
                    }
                    if (EPI == 0) {
                        float* C = (float*)Cv;
                        float2 o; o.x = v0; o.y = v1;
                        *(float2*)&C[(long)r * ldc + c] = o;
                    } else {
                        __nv_bfloat16* Cs = (__nv_bfloat16*)Cv;
                        __nv_bfloat16 h0, l0, h1, l1;
                        split2(v0, h0, l0); split2(v1, h1, l1);
                        __nv_bfloat162 hp, lp;
                        hp.x = h0; hp.y = h1; lp.x = l0; lp.y = l1;
                        *(__nv_bfloat162*)&Cs[(long)r * ldc + c]         = hp;
                        *(__nv_bfloat162*)&Cs[(long)r * ldc + c + loOff] = lp;
                    }
                }
            }
        }
    }
}

// =======================================================================
// Fused flash attention (round-11/13 proven, expf).
// =======================================================================
__global__ void __launch_bounds__(256) flash_kernel(
    const __nv_bfloat16* __restrict__ Qs,
    const __nv_bfloat16* __restrict__ Ks,
    const __nv_bfloat16* __restrict__ VTs,
    __nv_bfloat16* __restrict__ AOs)
{
    constexpr int LDS = 72;
    constexpr int LDV = 136;
    constexpr int QSZ = 128 * LDS * 2;
    constexpr int KSZ = 128 * LDS * 2;
    constexpr int VSZ = 64 * LDV * 2;
    constexpr int FST = 2 * QSZ;
    constexpr int STG = 2 * KSZ + 2 * VSZ;

    extern __shared__ __align__(16) char sm[];
    const uint32_t smb = smem_to_u32(sm);
    const int bh = blockIdx.x, b = bh >> 4, h = bh & 15;
    const int s0 = blockIdx.y * 128;
    const int tid = threadIdx.x, lane = tid & 31, wid = tid >> 5;

    const long qrow0 = (long)(b * SS + s0);
    {
        #pragma unroll
        for (int hf = 0; hf < 2; hf++) {
            const uint32_t sq = smb + hf * QSZ;
            const long colq = h * HDIM + (hf ? DMODEL : 0);
            #pragma unroll
            for (int it = 0; it < 4; it++) {
                const int idx = tid + it * 256;
                const int row = idx >> 3, c = idx & 7;
                cp_async16(sq + row * (LDS * 2) + c * 16,
                           Qs + (qrow0 + row) * (2 * DMODEL) + colq + c * 8);
            }
        }
        CP_COMMIT();
    }

    auto load_kv = [&](int buf, int jt) {
        const uint32_t base = smb + FST + buf * STG;
        const int j0 = jt * 128;
        #pragma unroll
        for (int hf = 0; hf < 2; hf++) {
            const uint32_t sk = base + hf * KSZ;
            const long colk = h * HDIM + (hf ? DMODEL : 0);
            #pragma unroll
            for (int it = 0; it < 4; it++) {
                const int idx = tid + it * 256;
                const int row = idx >> 3, c = idx & 7;
                cp_async16(sk + row * (LDS * 2) + c * 16,
                           Ks + ((long)(b * SS + j0 + row)) * (2 * DMODEL) + colk + c * 8);
            }
        }
        #pragma unroll
        for (int hf = 0; hf < 2; hf++) {
            const uint32_t sv = base + 2 * KSZ + hf * VSZ;
            const long colv = j0 + (hf ? SS : 0);
            #pragma unroll
            for (int it = 0; it < 4; it++) {
                const int idx = tid + it * 256;
                const int row = idx >> 4, c = idx & 15;
                cp_async16(sv + row * (LDV * 2) + c * 16,
                           VTs + ((long)(bh * HDIM + row)) * (2 * SS) + colv + c * 8);
            }
        }
        CP_COMMIT();
    };

    const int aRow = (lane & 7) + ((lane >> 3) & 1) * 8;
    const int aK   = (lane >> 4) * 8;
    const int bN   = ((lane >> 4) * 8) + (lane & 7);
    const int bK   = ((lane >> 3) & 1) * 8;
    const int mrow = wid * 16 + aRow;

    float oacc[8][4];
    #pragma unroll
    for (int n = 0; n < 8; n++)
        #pragma unroll
        for (int j = 0; j < 4; j++) oacc[n][j] = 0.f;
    float m0v = -INFINITY, m1v = -INFINITY, l0 = 0.f, l1 = 0.f;

    load_kv(0, 0);
    for (int jt = 0; jt < 8; jt++) {
        if (jt + 1 < 8) { load_kv((jt + 1) & 1, jt + 1); CP_WAIT(1); }
        else            { CP_WAIT(0); }
        __syncthreads();
        const uint32_t base = smb + FST + (jt & 1) * STG;
        const uint32_t sKhi = base, sKlo = base + KSZ;
        const uint32_t sVhi = base + 2 * KSZ, sVlo = sVhi + VSZ;
        const uint32_t sQhi = smb, sQlo = smb + QSZ;

        float sacc[16][4];
        #pragma unroll
        for (int n = 0; n < 16; n++)
            #pragma unroll
            for (int j = 0; j < 4; j++) sacc[n][j] = 0.f;

        #pragma unroll
        for (int k16 = 0; k16 < 4; k16++) {
            const int ka = k16 * 16 + aK;
            const int kb = k16 * 16 + bK;
            uint32_t qh[4], ql[4], kf[8][4];
            ldsm_x4(sQhi + (mrow * LDS + ka) * 2, qh[0], qh[1], qh[2], qh[3]);
            #pragma unroll
            for (int jn = 0; jn < 8; jn++) {
                const int n = jn * 16 + bN;
                ldsm_x4(sKhi + (n * LDS + kb) * 2, kf[jn][0], kf[jn][1], kf[jn][2], kf[jn][3]);
            }
            #pragma unroll
            for (int n = 0; n < 16; n++)
                mma16816(sacc[n], qh, kf[n >> 1][(n & 1) * 2], kf[n >> 1][(n & 1) * 2 + 1]);
            ldsm_x4(sQlo + (mrow * LDS + ka) * 2, ql[0], ql[1], ql[2], ql[3]);
            #pragma unroll
            for (int n = 0; n < 16; n++)
                mma16816(sacc[n], ql, kf[n >> 1][(n & 1) * 2], kf[n >> 1][(n & 1) * 2 + 1]);
            #pragma unroll
            for (int jn = 0; jn < 8; jn++) {
                const int n = jn * 16 + bN;
                ldsm_x4(sKlo + (n * LDS + kb) * 2, kf[jn][0], kf[jn][1], kf[jn][2], kf[jn][3]);
            }
            #pragma unroll
            for (int n = 0; n < 16; n++)
                mma16816(sacc[n], qh, kf[n >> 1][(n & 1) * 2], kf[n >> 1][(n & 1) * 2 + 1]);
        }

        float mx0 = -INFINITY, mx1 = -INFINITY;
        #pragma unroll
        for (int n = 0; n < 16; n++) {
            mx0 = fmaxf(mx0, fmaxf(sacc[n][0], sacc[n][1]));
            mx1 = fmaxf(mx1, fmaxf(sacc[n][2], sacc[n][3]));
        }
        mx0 = fmaxf(mx0, __shfl_xor_sync(0xffffffffu, mx0, 1));
        mx0 = fmaxf(mx0, __shfl_xor_sync(0xffffffffu, mx0, 2));
        mx1 = fmaxf(mx1, __shfl_xor_sync(0xffffffffu, mx1, 1));
        mx1 = fmaxf(mx1, __shfl_xor_sync(0xffffffffu, mx1, 2));
        const float mn0 = fmaxf(m0v, mx0), mn1 = fmaxf(m1v, mx1);
        const float al0 = expf(m0v - mn0), al1 = expf(m1v - mn1);
        m0v = mn0; m1v = mn1;
        float s0l = 0.f, s1l = 0.f;
        #pragma unroll
        for (int n = 0; n < 16; n++) {
            sacc[n][0] = expf(sacc[n][0] - mn0);
            sacc[n][1] = expf(sacc[n][1] - mn0);
            sacc[n][2] = expf(sacc[n][2] - mn1);
            sacc[n][3] = expf(sacc[n][3] - mn1);
            s0l += sacc[n][0] + sacc[n][1];
            s1l += sacc[n][2] + sacc[n][3];
        }
        s0l += __shfl_xor_sync(0xffffffffu, s0l, 1);
        s0l += __shfl_xor_sync(0xffffffffu, s0l, 2);
        s1l += __shfl_xor_sync(0xffffffffu, s1l, 1);
        s1l += __shfl_xor_sync(0xffffffffu, s1l, 2);
        l0 = l0 * al0 + s0l;
        l1 = l1 * al1 + s1l;
        #pragma unroll
        for (int n = 0; n < 8; n++) {
            oacc[n][0] *= al0; oacc[n][1] *= al0;
            oacc[n][2] *= al1; oacc[n][3] *= al1;
        }

        #pragma unroll
        for (int kj = 0; kj < 8; kj++) {
            const int t0 = kj * 2, t1 = kj * 2 + 1;
            uint32_t ahf[4], alf[4];
            {
                __nv_bfloat16 h0, l0b, h1, l1b;
                split2(sacc[t0][0], h0, l0b); split2(sacc[t0][1], h1, l1b);
                ahf[0] = packbf(__bfloat162float(h0), __bfloat162float(h1));
                alf[0] = packbf(__bfloat162float(l0b), __bfloat162float(l1b));
                split2(sacc[t0][2], h0, l0b); split2(sacc[t0][3], h1, l1b);
                ahf[1] = packbf(__bfloat162float(h0), __bfloat162float(h1));
                alf[1] = packbf(__bfloat162float(l0b), __bfloat162float(l1b));
                split2(sacc[t1][0], h0, l0b); split2(sacc[t1][1], h1, l1b);
                ahf[2] = packbf(__bfloat162float(h0), __bfloat162float(h1));
                alf[2] = packbf(__bfloat162float(l0b), __bfloat162float(l1b));
                split2(sacc[t1][2], h0, l0b); split2(sacc[t1][3], h1, l1b);
                ahf[3] = packbf(__bfloat162float(h0), __bfloat162float(h1));
                alf[3] = packbf(__bfloat162float(l0b), __bfloat162float(l1b));
            }
            const int kb2 = kj * 16 + bK;
            uint32_t vf[4][4];
            #pragma unroll
            for (int nb = 0; nb < 4; nb++) {
                const int n = nb * 16 + bN;
                ldsm_x4(sVhi + (n * LDV + kb2) * 2, vf[nb][0], vf[nb][1], vf[nb][2], vf[nb][3]);
            }
            #pragma unroll
            for (int n = 0; n < 8; n++)
                mma16816(oacc[n], ahf, vf[n >> 1][(n & 1) * 2], vf[n >> 1][(n & 1) * 2 + 1]);
            #pragma unroll
            for (int n = 0; n < 8; n++)
                mma16816(oacc[n], alf, vf[n >> 1][(n & 1) * 2], vf[n >> 1][(n & 1) * 2 + 1]);
            #pragma unroll
            for (int nb = 0; nb < 4; nb++) {
                const int n = nb * 16 + bN;
                ldsm_x4(sVlo + (n * LDV + kb2) * 2, vf[nb][0], vf[nb][1], vf[nb][2], vf[nb][3]);
            }
            #pragma unroll
            for (int n = 0; n < 8; n++)
                mma16816(oacc[n], ahf, vf[n >> 1][(n & 1) * 2], vf[n >> 1][(n & 1) * 2 + 1]);
        }
        __syncthreads();
    }

    const int g = lane >> 2, tig = lane & 3;
    const float inv0 = 1.0f / l0, inv1 = 1.0f / l1;
    #pragma unroll
    for (int n = 0; n < 8; n++) {
        const int d = n * 8 + tig * 2;
        #pragma unroll
        for (int half = 0; half < 2; half++) {
            const long r = qrow0 + wid * 16 + g + half * 8;
            const float inv = half ? inv1 : inv0;
            const float v0 = oacc[n][half * 2 + 0] * inv;
            const float v1 = oacc[n][half * 2 + 1] * inv;
            __nv_bfloat16 h0, lo0, h1, lo1;
            split2(v0, h0, lo0); split2(v1, h1, lo1);
            __nv_bfloat162 hp, lp;
            hp.x = h0; hp.y = h1; lp.x = lo0; lp.y = lo1;
            __nv_bfloat16* dst = AOs + r * (2 * DMODEL) + h * HDIM + d;
            *(__nv_bfloat162*)dst            = hp;
            *(__nv_bfloat162*)(dst + DMODEL) = lp;
        }
    }
}

// ---------------- reductions ----------------
__device__ __forceinline__ float block_reduce_sum(float v, float* sh) {
    #pragma unroll
    for (int o = 16; o; o >>= 1) v += __shfl_xor_sync(0xffffffffu, v, o);
    int warp = threadIdx.x >> 5, lane = threadIdx.x & 31;
    if (lane == 0) sh[warp] = v;
    __syncthreads();
    if (threadIdx.x < 8) {
        float x = sh[threadIdx.x];
        #pragma unroll
        for (int o = 4; o; o >>= 1) x += __shfl_xor_sync(0xffu, x, o);
        if (threadIdx.x == 0) sh[0] = x;
    }
    __syncthreads();
    float r = sh[0];
    __syncthreads();
    return r;
}

// ---------------- Ebar ----------------
__global__ void ebar_kernel(const float* __restrict__ rel) {
    const int j = blockIdx.x, d = threadIdx.x;
    const float* r0 = rel + (long)(SS - 1 - j) * HDIM + d;
    float s = 0.f;
    #pragma unroll 4
    for (int k = 0; k < SS; k++) s += r0[(long)k * HDIM];
    g_EB[j * HDIM + d] = s * (1.0f / SS);
}

// ---------------- split fp32 [R,K] -> bf16 [R, 2K] (initial x only) ----------------
__global__ void __launch_bounds__(256) split_kernel(
    const float* __restrict__ in, __nv_bfloat16* __restrict__ out, long n, int kshift)
{
    const long i4 = ((long)blockIdx.x * 256 + threadIdx.x) * 4;
    if (i4 >= n) return;
    const long row = i4 >> kshift;
    const int  K   = 1 << kshift;
    const int  col = (int)(i4 & (K - 1));
    const float4 v = *(const float4*)&in[i4];
    bh4 hi, lo;
    split2(v.x, hi.h[0], lo.h[0]); split2(v.y, hi.h[1], lo.h[1]);
    split2(v.z, hi.h[2], lo.h[2]); split2(v.w, hi.h[3], lo.h[3]);
    *(bh4*)&out[row * 2 * K + col]     = hi;
    *(bh4*)&out[row * 2 * K + K + col] = lo;
}

// ---------------- LN(xin + add) -> fp32 out + split out ----------------
__global__ void __launch_bounds__(256) ln_kernel(
    const float* __restrict__ xin, const float* __restrict__ add,
    const float* __restrict__ g, const float* __restrict__ be,
    float* __restrict__ out, __nv_bfloat16* __restrict__ outs)
{
    __shared__ float sh[8];
    const long row = blockIdx.x;
    const int t = threadIdx.x;
    const float4 a  = *(const float4*)&xin[row * DMODEL + t * 4];
    const float4 b2 = *(const float4*)&add[row * DMODEL + t * 4];
    float y[4] = {a.x + b2.x, a.y + b2.y, a.z + b2.z, a.w + b2.w};
    float s = y[0] + y[1] + y[2] + y[3];
    s = block_reduce_sum(s, sh);
    const float mean = s * (1.0f / DMODEL);
    float q = 0.f;
    #pragma unroll
    for (int i = 0; i < 4; i++) { const float d = y[i] - mean; q += d * d; }
    q = block_reduce_sum(q, sh);
    const float rstd = rsqrtf(q * (1.0f / DMODEL) + 1e-5f);
    const float4 gg = *(const float4*)&g[t * 4];
    const float4 bb = *(const float4*)&be[t * 4];
    float o[4];
    o[0] = (y[0] - mean) * rstd * gg.x + bb.x;
    o[1] = (y[1] - mean) * rstd * gg.y + bb.y;
    o[2] = (y[2] - mean) * rstd * gg.z + bb.z;
    o[3] = (y[3] - mean) * rstd * gg.w + bb.w;
    *(float4*)&out[row * DMODEL + t * 4] = *(float4*)o;
    bh4 hi, lo;
    #pragma unroll
    for (int i = 0; i < 4; i++) split2(o[i], hi.h[i], lo.h[i]);
    *(bh4*)&outs[row * 2 * DMODEL + t * 4]          = hi;
    *(bh4*)&outs[row * 2 * DMODEL + DMODEL + t * 4] = lo;
}

// ---------------- host ----------------
extern "C" void kernel_launch(void* const* d_in, const int* in_sizes, int n_in,
                              void* d_out, int out_size)
{
    (void)in_sizes; (void)n_in; (void)out_size;
    const float* x   = (const float*)d_in[0];
    const float* Wq  = (const float*)d_in[1];
    const float* bq  = (const float*)d_in[2];
    const float* Wk  = (const float*)d_in[3];
    const float* bk  = (const float*)d_in[4];
    const float* Wv  = (const float*)d_in[5];
    const float* bv  = (const float*)d_in[6];
    const float* Wo  = (const float*)d_in[7];
    const float* bo  = (const float*)d_in[8];
    const float* rel = (const float*)d_in[9];
    const float* W1  = (const float*)d_in[10];
    const float* b1  = (const float*)d_in[11];
    const float* W2  = (const float*)d_in[12];
    const float* b2  = (const float*)d_in[13];
    const float* g1  = (const float*)d_in[14];
    const float* be1 = (const float*)d_in[15];
    const float* g2  = (const float*)d_in[16];
    const float* be2 = (const float*)d_in[17];
    float* out = (float*)d_out;

    float *pX, *pT1, *pX1, *pEB;
    __nv_bfloat16 *pXs, *pQs, *pKs, *pVTs, *pAOs, *pX1s, *pHs;
    cudaGetSymbolAddress((void**)&pX,   g_X);
    cudaGetSymbolAddress((void**)&pXs,  g_Xs);
    cudaGetSymbolAddress((void**)&pQs,  g_Qs);
    cudaGetSymbolAddress((void**)&pKs,  g_Ks);
    cudaGetSymbolAddress((void**)&pVTs, g_VTs);
    cudaGetSymbolAddress((void**)&pAOs, g_AOs);
    cudaGetSymbolAddress((void**)&pT1,  g_T1);
    cudaGetSymbolAddress((void**)&pX1,  g_X1);
    cudaGetSymbolAddress((void**)&pX1s, g_X1s);
    cudaGetSymbolAddress((void**)&pHs,  g_Hs);
    cudaGetSymbolAddress((void**)&pEB,  g_EB);

    constexpr int LDS = 72;
    const int SMEM  = 2 * (2 * 128 * LDS * 2 + 2 * 64 * LDS * 2);  // 110592
    const int FSMEM = 2 * (128 * LDS * 2) + 2 * (2 * 128 * LDS * 2 + 2 * 64 * 136 * 2); // 180224
    cudaFuncSetAttribute((void*)mma_gemm<0>, cudaFuncAttributeMaxDynamicSharedMemorySize, SMEM);
    cudaFuncSetAttribute((void*)mma_gemm<1>, cudaFuncAttributeMaxDynamicSharedMemorySize, SMEM);
    cudaFuncSetAttribute((void*)mma_gemm<2>, cudaFuncAttributeMaxDynamicSharedMemorySize, SMEM);
    cudaFuncSetAttribute((void*)mma_gemm<3>, cudaFuncAttributeMaxDynamicSharedMemorySize, SMEM);
    cudaFuncSetAttribute((void*)mma_gemm<4>, cudaFuncAttributeMaxDynamicSharedMemorySize, SMEM);
    cudaFuncSetAttribute((void*)flash_kernel, cudaFuncAttributeMaxDynamicSharedMemorySize, FSMEM);

    const dim3 blk(256);
    const dim3 blkG(128);

    split_kernel<<<(NTOK * DMODEL) / 1024, blk>>>(x, pXs, (long)NTOK * DMODEL, 10);

    for (int l = 0; l < NLAYER; l++) {
        const float* xin  = (l == 0) ? x : pX;
        const float* Wq_l = Wq + (long)l * DMODEL * DMODEL;
        const float* Wk_l = Wk + (long)l * DMODEL * DMODEL;
        const float* Wv_l = Wv + (long)l * DMODEL * DMODEL;
        const float* Wo_l = Wo + (long)l * DMODEL * DMODEL;
        const float* W1_l = W1 + (long)l * DFFN * DMODEL;
        const float* W2_l = W2 + (long)l * DMODEL * DFFN;
        const float* bq_l = bq + (long)l * DMODEL;
        const float* bk_l = bk + (long)l * DMODEL;
        const float* bv_l = bv + (long)l * DMODEL;
        const float* bo_l = bo + (long)l * DMODEL;
        const float* b1_l = b1 + (long)l * DFFN;
        const float* b2_l = b2 + (long)l * DMODEL;
        const float* g1_l = g1 + (long)l * DMODEL;
        const float* be1_l= be1+ (long)l * DMODEL;
        const float* g2_l = g2 + (long)l * DMODEL;
        const float* be2_l= be2+ (long)l * DMODEL;
        const float* rel_l= rel+ (long)l * NREL * HDIM;

        ebar_kernel<<<SS, HDIM>>>(rel_l);

        // Q projection -> split Qs
        mma_gemm<1><<<dim3(16,16,1), blkG, SMEM>>>(
            pXs, 2*DMODEL, 64, DMODEL, Wq_l, DMODEL, bq_l, nullptr,
            pQs, 2*DMODEL, DMODEL, 16);

        // K projection -> K' = K/8 + Ebar -> split Ks
        mma_gemm<3><<<dim3(16,16,1), blkG, SMEM>>>(
            pXs, 2*DMODEL, 64, DMODEL, Wk_l, DMODEL, bk_l, pEB,
            pKs, 2*DMODEL, DMODEL, 16);

        // V projection -> split-transposed VTs directly (fused vtrans)
        mma_gemm<4><<<dim3(16,16,1), blkG, SMEM>>>(
            pXs, 2*DMODEL, 64, DMODEL, Wv_l, DMODEL, bv_l, nullptr,
            pVTs, 0, 0, 16);

        // fused attention: QK' -> softmax -> PV -> split AO
        flash_kernel<<<dim3(BB*NH, SS/128), blk, FSMEM>>>(pQs, pKs, pVTs, pAOs);

        // output projection -> fp32 T1
        mma_gemm<0><<<dim3(16,16,1), blkG, SMEM>>>(
            pAOs, 2*DMODEL, 64, DMODEL, Wo_l, DMODEL, bo_l, nullptr,
            pT1, DMODEL, 0, 16);

        ln_kernel<<<NTOK, blk>>>(xin, pT1, g1_l, be1_l, pX1, pX1s);

        // FFN1 (gelu) -> split Hs
        mma_gemm<2><<<dim3(64,16,1), blkG, SMEM>>>(
            pX1s, 2*DMODEL, 64, DMODEL, W1_l, DMODEL, b1_l, nullptr,
            pHs, 2*DFFN, DFFN, 16);

        // FFN2 -> fp32 T1
        mma_gemm<0><<<dim3(16,16,1), blkG, SMEM>>>(
            pHs, 2*DFFN, 64, DFFN, W2_l, DFFN, b2_l, nullptr,
            pT1, DMODEL, 0, 64);

        ln_kernel<<<NTOK, blk>>>(pX1, pT1, g2_l, be2_l, (l == NLAYER-1) ? out : pX, pXs);
    }
}

// round 17
// speedup vs baseline: 1.0744x; 1.0507x over previous
#include <cuda_runtime.h>
#include <cuda_bf16.h>
#include <cstdint>
#include <math.h>

#define BB   2
#define SS   1024
#define DMODEL 1024
#define NH   16
#define NLAYER 4
#define DFFN 4096
#define HDIM 64
#define NTOK (BB*SS)          // 2048
#define NREL (2*SS-1)         // 2047

// ---------------- static scratch ----------------
__device__ float          g_X  [NTOK*DMODEL];            // fp32 activations
__device__ __nv_bfloat16  g_Xs [NTOK*2*DMODEL];          // split of layer input
__device__ __nv_bfloat16  g_Qs [NTOK*2*DMODEL];
__device__ __nv_bfloat16  g_Ks [NTOK*2*DMODEL];          // split of K' = K/8 + Ebar
__device__ __nv_bfloat16  g_VTs[(size_t)BB*NH*HDIM*2*SS];// per-head V^T split
__device__ __nv_bfloat16  g_AOs[NTOK*2*DMODEL];
__device__ float          g_T1 [NTOK*DMODEL];
__device__ float          g_X1 [NTOK*DMODEL];
__device__ __nv_bfloat16  g_X1s[NTOK*2*DMODEL];
__device__ __nv_bfloat16  g_Hs [(size_t)NTOK*2*DFFN];
__device__ float          g_EB [SS*HDIM];

// ---------------- helpers ----------------
__device__ __forceinline__ uint32_t smem_to_u32(const void* p) {
    uint32_t a;
    asm("{ .reg .u64 t; cvta.to.shared.u64 t, %1; cvt.u32.u64 %0, t; }" : "=r"(a) : "l"(p));
    return a;
}
__device__ __forceinline__ void cp_async16(uint32_t s, const void* g) {
    asm volatile("cp.async.cg.shared.global [%0], [%1], 16;" :: "r"(s), "l"(g) : "memory");
}
#define CP_COMMIT() asm volatile("cp.async.commit_group;" ::: "memory")
#define CP_WAIT(n)  asm volatile("cp.async.wait_group %0;" :: "n"(n) : "memory")

__device__ __forceinline__ void ldsm_x4(uint32_t addr, uint32_t& r0, uint32_t& r1,
                                        uint32_t& r2, uint32_t& r3) {
    asm volatile("ldmatrix.sync.aligned.m8n8.x4.shared.b16 {%0,%1,%2,%3}, [%4];"
                 : "=r"(r0), "=r"(r1), "=r"(r2), "=r"(r3) : "r"(addr));
}
__device__ __forceinline__ void mma16816(float* c, const uint32_t* a, uint32_t b0, uint32_t b1) {
    asm volatile(
        "mma.sync.aligned.m16n8k16.row.col.f32.bf16.bf16.f32 "
        "{%0,%1,%2,%3}, {%4,%5,%6,%7}, {%8,%9}, {%0,%1,%2,%3};"
        : "+f"(c[0]), "+f"(c[1]), "+f"(c[2]), "+f"(c[3])
        : "r"(a[0]), "r"(a[1]), "r"(a[2]), "r"(a[3]), "r"(b0), "r"(b1));
}

struct __align__(8) bh4 { __nv_bfloat16 h[4]; };
__device__ __forceinline__ void split2(float v, __nv_bfloat16& hi, __nv_bfloat16& lo) {
    hi = __float2bfloat16(v);
    lo = __float2bfloat16(v - __bfloat162float(hi));
}

// ---- fast packed split: bit-identical to split2/packbf, ~half the ops ----
// pack_hi2(v0,v1): bf16x2 with low=RN(v0), high=RN(v1)  (one cvt.rn.bf16x2.f32)
__device__ __forceinline__ uint32_t pack_hi2(float v0, float v1) {
    uint32_t r;
    asm("cvt.rn.bf16x2.f32 %0, %1, %2;" : "=r"(r) : "f"(v1), "f"(v0));
    return r;
}
// lo residual: hi halves reconstructed exactly via bit ops (bf16->f32 == <<16)
__device__ __forceinline__ uint32_t pack_lo2(uint32_t hi, float v0, float v1) {
    const float h0 = __uint_as_float(hi << 16);
    const float h1 = __uint_as_float(hi & 0xFFFF0000u);
    uint32_t r;
    asm("cvt.rn.bf16x2.f32 %0, %1, %2;" : "=r"(r) : "f"(v1 - h1), "f"(v0 - h0));
    return r;
}

// =======================================================================
// HMMA split-fp32 GEMM with IN-KERNEL weight splitting (round-13 proven).
// A: split bf16 [hi|lo] rows via cp.async; B: raw fp32 weights, reg-staged
// LDG.128 -> packed split -> Bhi/Blo smem. CTA 128 thr, 4 warps (2m x 2n),
// warp tile 64x32, block 128x64, 2-stage, 110.6 KB smem, 2 CTAs/SM.
// EPI: 0 f32+bias | 1 split+bias | 2 split+bias+gelu | 3 split+bias+kadjust
//      4 V-mode: bias, split, per-head TRANSPOSED store into VTs
// =======================================================================
template<int EPI>
__global__ void __launch_bounds__(128) mma_gemm(
    const __nv_bfloat16* __restrict__ A, long lda, long csA, long loA,
    const float* __restrict__ B, long ldb,
    const float* __restrict__ bias, const float* __restrict__ EB,
    void* __restrict__ Cv, long ldc, long loOff, int T)
{
    extern __shared__ __align__(16) char smraw[];
    constexpr int LDS = 72;
    constexpr int ASZ = 128 * LDS * 2;
    constexpr int BSZ = 64 * LDS * 2;
    constexpr int STAGE = 2 * ASZ + 2 * BSZ;

    const int tid = threadIdx.x;
    const int m0 = blockIdx.y * 128, n0 = blockIdx.x * 64;
    const int lane = tid & 31, wid = tid >> 5;
    const int warp_m = wid & 1, warp_n = wid >> 1;

    auto loadA = [&](int buf, int i) {
        const uint32_t base = smem_to_u32(smraw + (long)buf * STAGE);
        const long colA = (long)i * csA;
        #pragma unroll
        for (int h = 0; h < 2; h++) {
            const long ca = colA + (h ? loA : 0);
            const uint32_t sa = base + h * ASZ;
            #pragma unroll
            for (int it = 0; it < 8; it++) {
                const int idx = tid + it * 128;
                const int row = idx >> 3, c = idx & 7;
                cp_async16(sa + row * (LDS * 2) + c * 16,
                           A + (long)(m0 + row) * lda + ca + c * 8);
            }
        }
        CP_COMMIT();
    };

    float breg[32];
    auto ldgB = [&](int i) {
        const long col = (long)i * 64;
        #pragma unroll
        for (int it = 0; it < 8; it++) {
            const int idx = tid + it * 128;
            const int row = idx >> 4, c = idx & 15;
            *(float4*)&breg[it * 4] =
                *(const float4*)&B[(long)(n0 + row) * ldb + col + c * 4];
        }
    };
    auto stsB = [&](int buf) {
        char* base = smraw + (long)buf * STAGE + 2 * ASZ;
        #pragma unroll
        for (int it = 0; it < 8; it++) {
            const int idx = tid + it * 128;
            const int row = idx >> 4, c = idx & 15;
            const uint32_t h0 = pack_hi2(breg[it*4+0], breg[it*4+1]);
            const uint32_t h1 = pack_hi2(breg[it*4+2], breg[it*4+3]);
            const uint32_t l0 = pack_lo2(h0, breg[it*4+0], breg[it*4+1]);
            const uint32_t l1 = pack_lo2(h1, breg[it*4+2], breg[it*4+3]);
            uint2 hv; hv.x = h0; hv.y = h1;
            uint2 lv; lv.x = l0; lv.y = l1;
            *(uint2*)(base + row * (LDS * 2) + c * 8)       = hv;
            *(uint2*)(base + BSZ + row * (LDS * 2) + c * 8) = lv;
        }
    };

    float acc[4][4][4];
    #pragma unroll
    for (int mi = 0; mi < 4; mi++)
        #pragma unroll
        for (int ni = 0; ni < 4; ni++)
            #pragma unroll
            for (int j = 0; j < 4; j++) acc[mi][ni][j] = 0.f;

    const int aRow = (lane & 7) + ((lane >> 3) & 1) * 8;
    const int aK   = (lane >> 4) * 8;
    const int bN   = ((lane >> 4) * 8) + (lane & 7);
    const int bK   = ((lane >> 3) & 1) * 8;

    auto compute_stage = [&](int buf) {
        const uint32_t base = smem_to_u32(smraw + (long)buf * STAGE);
        const uint32_t sAhi = base, sAlo = base + ASZ;
        const uint32_t sBhi = base + 2 * ASZ, sBlo = sBhi + BSZ;
        #pragma unroll
        for (int k16 = 0; k16 < 4; k16++) {
            const int ka = k16 * 16 + aK;
            const int kb = k16 * 16 + bK;
            uint32_t ah[4][4], al[4][4], bhf[2][4], blf[2][4];
            #pragma unroll
            for (int mi = 0; mi < 4; mi++) {
                const int m = warp_m * 64 + mi * 16 + aRow;
                ldsm_x4(sAhi + (m * LDS + ka) * 2, ah[mi][0], ah[mi][1], ah[mi][2], ah[mi][3]);
            }
            #pragma unroll
            for (int nb = 0; nb < 2; nb++) {
                const int n = warp_n * 32 + nb * 16 + bN;
                ldsm_x4(sBhi + (n * LDS + kb) * 2, bhf[nb][0], bhf[nb][1], bhf[nb][2], bhf[nb][3]);
            }
            #pragma unroll
            for (int mi = 0; mi < 4; mi++)
                #pragma unroll
                for (int ni = 0; ni < 4; ni++)
                    mma16816(acc[mi][ni], ah[mi], bhf[ni >> 1][(ni & 1) * 2], bhf[ni >> 1][(ni & 1) * 2 + 1]);
            #pragma unroll
            for (int mi = 0; mi < 4; mi++) {
                const int m = warp_m * 64 + mi * 16 + aRow;
                ldsm_x4(sAlo + (m * LDS + ka) * 2, al[mi][0], al[mi][1], al[mi][2], al[mi][3]);
            }
            #pragma unroll
            for (int mi = 0; mi < 4; mi++)
                #pragma unroll
                for (int ni = 0; ni < 4; ni++)
                    mma16816(acc[mi][ni], al[mi], bhf[ni >> 1][(ni & 1) * 2], bhf[ni >> 1][(ni & 1) * 2 + 1]);
            #pragma unroll
            for (int nb = 0; nb < 2; nb++) {
                const int n = warp_n * 32 + nb * 16 + bN;
                ldsm_x4(sBlo + (n * LDS + kb) * 2, blf[nb][0], blf[nb][1], blf[nb][2], blf[nb][3]);
            }
            #pragma unroll
            for (int mi = 0; mi < 4; mi++)
                #pragma unroll
                for (int ni = 0; ni < 4; ni++)
                    mma16816(acc[mi][ni], ah[mi], blf[ni >> 1][(ni & 1) * 2], blf[ni >> 1][(ni & 1) * 2 + 1]);
        }
    };

    ldgB(0);
    loadA(0, 0);
    stsB(0);
    if (T > 1) ldgB(1);

    for (int t = 0; t < T; t++) {
        if (t + 1 < T) { loadA((t + 1) & 1, t + 1); CP_WAIT(1); }
        else           { CP_WAIT(0); }
        __syncthreads();
        compute_stage(t & 1);
        if (t + 1 < T) {
            stsB((t + 1) & 1);
            if (t + 2 < T) ldgB(t + 2);
        }
        __syncthreads();
    }

    const int g = lane >> 2, tig = lane & 3;

    if (EPI == 4) {
        // ---- V-mode: split + transpose via smem, coalesced store to VTs ----
        __nv_bfloat16* sth = (__nv_bfloat16*)smraw;          // [64 d][136 s] hi
        __nv_bfloat16* stl = sth + 64 * 136;                 // lo
        #pragma unroll
        for (int mi = 0; mi < 4; mi++)
            #pragma unroll
            for (int ni = 0; ni < 4; ni++)
                #pragma unroll
                for (int half = 0; half < 2; half++) {
                    const int rl = warp_m * 64 + mi * 16 + g + half * 8;
                    const int cl = warp_n * 32 + ni * 8 + tig * 2;
                    float v0 = acc[mi][ni][half * 2 + 0] + bias[n0 + cl];
                    float v1 = acc[mi][ni][half * 2 + 1] + bias[n0 + cl + 1];
                    __nv_bfloat16 h0, l0, h1, l1;
                    split2(v0, h0, l0); split2(v1, h1, l1);
                    sth[cl * 136 + rl] = h0;       stl[cl * 136 + rl] = l0;
                    sth[(cl + 1) * 136 + rl] = h1; stl[(cl + 1) * 136 + rl] = l1;
                }
        __syncthreads();
        const int b     = m0 >> 10;
        const int sbase = m0 & 1023;
        const int bh    = b * NH + (n0 >> 6);
        __nv_bfloat16* VT = (__nv_bfloat16*)Cv;
        #pragma unroll
        for (int it = 0; it < 16; it++) {
            const int idx = tid + it * 128;
            const int d   = idx >> 5;
            const int cs  = (idx & 31) * 4;
            bh4 vh = *(bh4*)&sth[d * 136 + cs];
            bh4 vl = *(bh4*)&stl[d * 136 + cs];
            const long base = ((long)bh * HDIM + d) * (2 * SS) + sbase + cs;
            *(bh4*)&VT[base]      = vh;
            *(bh4*)&VT[base + SS] = vl;
        }
    } else {
        #pragma unroll
        for (int mi = 0; mi < 4; mi++) {
            #pragma unroll
            for (int ni = 0; ni < 4; ni++) {
                #pragma unroll
                for (int half = 0; half < 2; half++) {
                    const int r = m0 + warp_m * 64 + mi * 16 + g + half * 8;
                    const int c = n0 + warp_n * 32 + ni * 8 + tig * 2;
                    float v0 = acc[mi][ni][half * 2 + 0];
                    float v1 = acc[mi][ni][half * 2 + 1];
                    if (bias) { v0 += bias[c]; v1 += bias[c + 1]; }
                    if (EPI == 3) {
                        const int sr = (r & (SS - 1)) * HDIM;
                        v0 = v0 * 0.125f + EB[sr + (c & (HDIM - 1))];
                        v1 = v1 * 0.125f + EB[sr + ((c + 1) & (HDIM - 1))];
                    }
                    if (EPI == 2) {
                        v0 = 0.5f * v0 * (1.0f + erff(v0 * 0.70710678118654752f));
                        v1 = 0.5f * v1 * (1.0f + erff(v1 * 0.70710678118654752f));
                    }
                    if (EPI == 0) {
                        float* C = (float*)Cv;
                        float2 o; o.x = v0; o.y = v1;
                        *(float2*)&C[(long)r * ldc + c] = o;
                    } else {
                        __nv_bfloat16* Cs = (__nv_bfloat16*)Cv;
                        const uint32_t hp = pack_hi2(v0, v1);
                        const uint32_t lp = pack_lo2(hp, v0, v1);
                        *(uint32_t*)&Cs[(long)r * ldc + c]         = hp;
                        *(uint32_t*)&Cs[(long)r * ldc + c + loOff] = lp;
                    }
                }
            }
        }
    }
}

// =======================================================================
// Fused flash attention (round-11/13 proven, expf) + packed P split.
// =======================================================================
__global__ void __launch_bounds__(256) flash_kernel(
    const __nv_bfloat16* __restrict__ Qs,
    const __nv_bfloat16* __restrict__ Ks,
    const __nv_bfloat16* __restrict__ VTs,
    __nv_bfloat16* __restrict__ AOs)
{
    constexpr int LDS = 72;
    constexpr int LDV = 136;
    constexpr int QSZ = 128 * LDS * 2;
    constexpr int KSZ = 128 * LDS * 2;
    constexpr int VSZ = 64 * LDV * 2;
    constexpr int FST = 2 * QSZ;
    constexpr int STG = 2 * KSZ + 2 * VSZ;

    extern __shared__ __align__(16) char sm[];
    const uint32_t smb = smem_to_u32(sm);
    const int bh = blockIdx.x, b = bh >> 4, h = bh & 15;
    const int s0 = blockIdx.y * 128;
    const int tid = threadIdx.x, lane = tid & 31, wid = tid >> 5;

    const long qrow0 = (long)(b * SS + s0);
    {
        #pragma unroll
        for (int hf = 0; hf < 2; hf++) {
            const uint32_t sq = smb + hf * QSZ;
            const long colq = h * HDIM + (hf ? DMODEL : 0);
            #pragma unroll
            for (int it = 0; it < 4; it++) {
                const int idx = tid + it * 256;
                const int row = idx >> 3, c = idx & 7;
                cp_async16(sq + row * (LDS * 2) + c * 16,
                           Qs + (qrow0 + row) * (2 * DMODEL) + colq + c * 8);
            }
        }
        CP_COMMIT();
    }

    auto load_kv = [&](int buf, int jt) {
        const uint32_t base = smb + FST + buf * STG;
        const int j0 = jt * 128;
        #pragma unroll
        for (int hf = 0; hf < 2; hf++) {
            const uint32_t sk = base + hf * KSZ;
            const long colk = h * HDIM + (hf ? DMODEL : 0);
            #pragma unroll
            for (int it = 0; it < 4; it++) {
                const int idx = tid + it * 256;
                const int row = idx >> 3, c = idx & 7;
                cp_async16(sk + row * (LDS * 2) + c * 16,
                           Ks + ((long)(b * SS + j0 + row)) * (2 * DMODEL) + colk + c * 8);
            }
        }
        #pragma unroll
        for (int hf = 0; hf < 2; hf++) {
            const uint32_t sv = base + 2 * KSZ + hf * VSZ;
            const long colv = j0 + (hf ? SS : 0);
            #pragma unroll
            for (int it = 0; it < 4; it++) {
                const int idx = tid + it * 256;
                const int row = idx >> 4, c = idx & 15;
                cp_async16(sv + row * (LDV * 2) + c * 16,
                           VTs + ((long)(bh * HDIM + row)) * (2 * SS) + colv + c * 8);
            }
        }
        CP_COMMIT();
    };

    const int aRow = (lane & 7) + ((lane >> 3) & 1) * 8;
    const int aK   = (lane >> 4) * 8;
    const int bN   = ((lane >> 4) * 8) + (lane & 7);
    const int bK   = ((lane >> 3) & 1) * 8;
    const int mrow = wid * 16 + aRow;

    float oacc[8][4];
    #pragma unroll
    for (int n = 0; n < 8; n++)
        #pragma unroll
        for (int j = 0; j < 4; j++) oacc[n][j] = 0.f;
    float m0v = -INFINITY, m1v = -INFINITY, l0 = 0.f, l1 = 0.f;

    load_kv(0, 0);
    for (int jt = 0; jt < 8; jt++) {
        if (jt + 1 < 8) { load_kv((jt + 1) & 1, jt + 1); CP_WAIT(1); }
        else            { CP_WAIT(0); }
        __syncthreads();
        const uint32_t base = smb + FST + (jt & 1) * STG;
        const uint32_t sKhi = base, sKlo = base + KSZ;
        const uint32_t sVhi = base + 2 * KSZ, sVlo = sVhi + VSZ;
        const uint32_t sQhi = smb, sQlo = smb + QSZ;

        float sacc[16][4];
        #pragma unroll
        for (int n = 0; n < 16; n++)
            #pragma unroll
            for (int j = 0; j < 4; j++) sacc[n][j] = 0.f;

        #pragma unroll
        for (int k16 = 0; k16 < 4; k16++) {
            const int ka = k16 * 16 + aK;
            const int kb = k16 * 16 + bK;
            uint32_t qh[4], ql[4], kf[8][4];
            ldsm_x4(sQhi + (mrow * LDS + ka) * 2, qh[0], qh[1], qh[2], qh[3]);
            #pragma unroll
            for (int jn = 0; jn < 8; jn++) {
                const int n = jn * 16 + bN;
                ldsm_x4(sKhi + (n * LDS + kb) * 2, kf[jn][0], kf[jn][1], kf[jn][2], kf[jn][3]);
            }
            #pragma unroll
            for (int n = 0; n < 16; n++)
                mma16816(sacc[n], qh, kf[n >> 1][(n & 1) * 2], kf[n >> 1][(n & 1) * 2 + 1]);
            ldsm_x4(sQlo + (mrow * LDS + ka) * 2, ql[0], ql[1], ql[2], ql[3]);
            #pragma unroll
            for (int n = 0; n < 16; n++)
                mma16816(sacc[n], ql, kf[n >> 1][(n & 1) * 2], kf[n >> 1][(n & 1) * 2 + 1]);
            #pragma unroll
            for (int jn = 0; jn < 8; jn++) {
                const int n = jn * 16 + bN;
                ldsm_x4(sKlo + (n * LDS + kb) * 2, kf[jn][0], kf[jn][1], kf[jn][2], kf[jn][3]);
            }
            #pragma unroll
            for (int n = 0; n < 16; n++)
                mma16816(sacc[n], qh, kf[n >> 1][(n & 1) * 2], kf[n >> 1][(n & 1) * 2 + 1]);
        }

        float mx0 = -INFINITY, mx1 = -INFINITY;
        #pragma unroll
        for (int n = 0; n < 16; n++) {
            mx0 = fmaxf(mx0, fmaxf(sacc[n][0], sacc[n][1]));
            mx1 = fmaxf(mx1, fmaxf(sacc[n][2], sacc[n][3]));
        }
        mx0 = fmaxf(mx0, __shfl_xor_sync(0xffffffffu, mx0, 1));
        mx0 = fmaxf(mx0, __shfl_xor_sync(0xffffffffu, mx0, 2));
        mx1 = fmaxf(mx1, __shfl_xor_sync(0xffffffffu, mx1, 1));
        mx1 = fmaxf(mx1, __shfl_xor_sync(0xffffffffu, mx1, 2));
        const float mn0 = fmaxf(m0v, mx0), mn1 = fmaxf(m1v, mx1);
        const float al0 = expf(m0v - mn0), al1 = expf(m1v - mn1);
        m0v = mn0; m1v = mn1;
        float s0l = 0.f, s1l = 0.f;
        #pragma unroll
        for (int n = 0; n < 16; n++) {
            sacc[n][0] = expf(sacc[n][0] - mn0);
            sacc[n][1] = expf(sacc[n][1] - mn0);
            sacc[n][2] = expf(sacc[n][2] - mn1);
            sacc[n][3] = expf(sacc[n][3] - mn1);
            s0l += sacc[n][0] + sacc[n][1];
            s1l += sacc[n][2] + sacc[n][3];
        }
        s0l += __shfl_xor_sync(0xffffffffu, s0l, 1);
        s0l += __shfl_xor_sync(0xffffffffu, s0l, 2);
        s1l += __shfl_xor_sync(0xffffffffu, s1l, 1);
        s1l += __shfl_xor_sync(0xffffffffu, s1l, 2);
        l0 = l0 * al0 + s0l;
        l1 = l1 * al1 + s1l;
        #pragma unroll
        for (int n = 0; n < 8; n++) {
            oacc[n][0] *= al0; oacc[n][1] *= al0;
            oacc[n][2] *= al1; oacc[n][3] *= al1;
        }

        #pragma unroll
        for (int kj = 0; kj < 8; kj++) {
            const int t0 = kj * 2, t1 = kj * 2 + 1;
            uint32_t ahf[4], alf[4];
            ahf[0] = pack_hi2(sacc[t0][0], sacc[t0][1]);
            alf[0] = pack_lo2(ahf[0], sacc[t0][0], sacc[t0][1]);
            ahf[1] = pack_hi2(sacc[t0][2], sacc[t0][3]);
            alf[1] = pack_lo2(ahf[1], sacc[t0][2], sacc[t0][3]);
            ahf[2] = pack_hi2(sacc[t1][0], sacc[t1][1]);
            alf[2] = pack_lo2(ahf[2], sacc[t1][0], sacc[t1][1]);
            ahf[3] = pack_hi2(sacc[t1][2], sacc[t1][3]);
            alf[3] = pack_lo2(ahf[3], sacc[t1][2], sacc[t1][3]);

            const int kb2 = kj * 16 + bK;
            uint32_t vf[4][4];
            #pragma unroll
            for (int nb = 0; nb < 4; nb++) {
                const int n = nb * 16 + bN;
                ldsm_x4(sVhi + (n * LDV + kb2) * 2, vf[nb][0], vf[nb][1], vf[nb][2], vf[nb][3]);
            }
            #pragma unroll
            for (int n = 0; n < 8; n++)
                mma16816(oacc[n], ahf, vf[n >> 1][(n & 1) * 2], vf[n >> 1][(n & 1) * 2 + 1]);
            #pragma unroll
            for (int n = 0; n < 8; n++)
                mma16816(oacc[n], alf, vf[n >> 1][(n & 1) * 2], vf[n >> 1][(n & 1) * 2 + 1]);
            #pragma unroll
            for (int nb = 0; nb < 4; nb++) {
                const int n = nb * 16 + bN;
                ldsm_x4(sVlo + (n * LDV + kb2) * 2, vf[nb][0], vf[nb][1], vf[nb][2], vf[nb][3]);
            }
            #pragma unroll
            for (int n = 0; n < 8; n++)
                mma16816(oacc[n], ahf, vf[n >> 1][(n & 1) * 2], vf[n >> 1][(n & 1) * 2 + 1]);
        }
        __syncthreads();
    }

    const int g = lane >> 2, tig = lane & 3;
    const float inv0 = 1.0f / l0, inv1 = 1.0f / l1;
    #pragma unroll
    for (int n = 0; n < 8; n++) {
        const int d = n * 8 + tig * 2;
        #pragma unroll
        for (int half = 0; half < 2; half++) {
            const long r = qrow0 + wid * 16 + g + half * 8;
            const float inv = half ? inv1 : inv0;
            const float v0 = oacc[n][half * 2 + 0] * inv;
            const float v1 = oacc[n][half * 2 + 1] * inv;
            const uint32_t hp = pack_hi2(v0, v1);
            const uint32_t lp = pack_lo2(hp, v0, v1);
            __nv_bfloat16* dst = AOs + r * (2 * DMODEL) + h * HDIM + d;
            *(uint32_t*)dst            = hp;
            *(uint32_t*)(dst + DMODEL) = lp;
        }
    }
}

// ---------------- reductions ----------------
__device__ __forceinline__ float block_reduce_sum(float v, float* sh) {
    #pragma unroll
    for (int o = 16; o; o >>= 1) v += __shfl_xor_sync(0xffffffffu, v, o);
    int warp = threadIdx.x >> 5, lane = threadIdx.x & 31;
    if (lane == 0) sh[warp] = v;
    __syncthreads();
    if (threadIdx.x < 8) {
        float x = sh[threadIdx.x];
        #pragma unroll
        for (int o = 4; o; o >>= 1) x += __shfl_xor_sync(0xffu, x, o);
        if (threadIdx.x == 0) sh[0] = x;
    }
    __syncthreads();
    float r = sh[0];
    __syncthreads();
    return r;
}

// ---------------- Ebar ----------------
__global__ void ebar_kernel(const float* __restrict__ rel) {
    const int j = blockIdx.x, d = threadIdx.x;
    const float* r0 = rel + (long)(SS - 1 - j) * HDIM + d;
    float s = 0.f;
    #pragma unroll 4
    for (int k = 0; k < SS; k++) s += r0[(long)k * HDIM];
    g_EB[j * HDIM + d] = s * (1.0f / SS);
}

// ---------------- split fp32 [R,K] -> bf16 [R, 2K] (initial x only) ----------------
__global__ void __launch_bounds__(256) split_kernel(
    const float* __restrict__ in, __nv_bfloat16* __restrict__ out, long n, int kshift)
{
    const long i4 = ((long)blockIdx.x * 256 + threadIdx.x) * 4;
    if (i4 >= n) return;
    const long row = i4 >> kshift;
    const int  K   = 1 << kshift;
    const int  col = (int)(i4 & (K - 1));
    const float4 v = *(const float4*)&in[i4];
    uint2 hv, lv;
    hv.x = pack_hi2(v.x, v.y); lv.x = pack_lo2(hv.x, v.x, v.y);
    hv.y = pack_hi2(v.z, v.w); lv.y = pack_lo2(hv.y, v.z, v.w);
    *(uint2*)&out[row * 2 * K + col]     = hv;
    *(uint2*)&out[row * 2 * K + K + col] = lv;
}

// ---------------- LN(xin + add) -> fp32 out + split out ----------------
__global__ void __launch_bounds__(256) ln_kernel(
    const float* __restrict__ xin, const float* __restrict__ add,
    const float* __restrict__ g, const float* __restrict__ be,
    float* __restrict__ out, __nv_bfloat16* __restrict__ outs)
{
    __shared__ float sh[8];
    const long row = blockIdx.x;
    const int t = threadIdx.x;
    const float4 a  = *(const float4*)&xin[row * DMODEL + t * 4];
    const float4 b2 = *(const float4*)&add[row * DMODEL + t * 4];
    float y[4] = {a.x + b2.x, a.y + b2.y, a.z + b2.z, a.w + b2.w};
    float s = y[0] + y[1] + y[2] + y[3];
    s = block_reduce_sum(s, sh);
    const float mean = s * (1.0f / DMODEL);
    float q = 0.f;
    #pragma unroll
    for (int i = 0; i < 4; i++) { const float d = y[i] - mean; q += d * d; }
    q = block_reduce_sum(q, sh);
    const float rstd = rsqrtf(q * (1.0f / DMODEL) + 1e-5f);
    const float4 gg = *(const float4*)&g[t * 4];
    const float4 bb = *(const float4*)&be[t * 4];
    float o[4];
    o[0] = (y[0] - mean) * rstd * gg.x + bb.x;
    o[1] = (y[1] - mean) * rstd * gg.y + bb.y;
    o[2] = (y[2] - mean) * rstd * gg.z + bb.z;
    o[3] = (y[3] - mean) * rstd * gg.w + bb.w;
    *(float4*)&out[row * DMODEL + t * 4] = *(float4*)o;
    uint2 hv, lv;
    hv.x = pack_hi2(o[0], o[1]); lv.x = pack_lo2(hv.x, o[0], o[1]);
    hv.y = pack_hi2(o[2], o[3]); lv.y = pack_lo2(hv.y, o[2], o[3]);
    *(uint2*)&outs[row * 2 * DMODEL + t * 4]          = hv;
    *(uint2*)&outs[row * 2 * DMODEL + DMODEL + t * 4] = lv;
}

// ---------------- host ----------------
extern "C" void kernel_launch(void* const* d_in, const int* in_sizes, int n_in,
                              void* d_out, int out_size)
{
    (void)in_sizes; (void)n_in; (void)out_size;
    const float* x   = (const float*)d_in[0];
    const float* Wq  = (const float*)d_in[1];
    const float* bq  = (const float*)d_in[2];
    const float* Wk  = (const float*)d_in[3];
    const float* bk  = (const float*)d_in[4];
    const float* Wv  = (const float*)d_in[5];
    const float* bv  = (const float*)d_in[6];
    const float* Wo  = (const float*)d_in[7];
    const float* bo  = (const float*)d_in[8];
    const float* rel = (const float*)d_in[9];
    const float* W1  = (const float*)d_in[10];
    const float* b1  = (const float*)d_in[11];
    const float* W2  = (const float*)d_in[12];
    const float* b2  = (const float*)d_in[13];
    const float* g1  = (const float*)d_in[14];
    const float* be1 = (const float*)d_in[15];
    const float* g2  = (const float*)d_in[16];
    const float* be2 = (const float*)d_in[17];
    float* out = (float*)d_out;

    float *pX, *pT1, *pX1, *pEB;
    __nv_bfloat16 *pXs, *pQs, *pKs, *pVTs, *pAOs, *pX1s, *pHs;
    cudaGetSymbolAddress((void**)&pX,   g_X);
    cudaGetSymbolAddress((void**)&pXs,  g_Xs);
    cudaGetSymbolAddress((void**)&pQs,  g_Qs);
    cudaGetSymbolAddress((void**)&pKs,  g_Ks);
    cudaGetSymbolAddress((void**)&pVTs, g_VTs);
    cudaGetSymbolAddress((void**)&pAOs, g_AOs);
    cudaGetSymbolAddress((void**)&pT1,  g_T1);
    cudaGetSymbolAddress((void**)&pX1,  g_X1);
    cudaGetSymbolAddress((void**)&pX1s, g_X1s);
    cudaGetSymbolAddress((void**)&pHs,  g_Hs);
    cudaGetSymbolAddress((void**)&pEB,  g_EB);

    constexpr int LDS = 72;
    const int SMEM  = 2 * (2 * 128 * LDS * 2 + 2 * 64 * LDS * 2);  // 110592
    const int FSMEM = 2 * (128 * LDS * 2) + 2 * (2 * 128 * LDS * 2 + 2 * 64 * 136 * 2); // 180224
    cudaFuncSetAttribute((void*)mma_gemm<0>, cudaFuncAttributeMaxDynamicSharedMemorySize, SMEM);
    cudaFuncSetAttribute((void*)mma_gemm<1>, cudaFuncAttributeMaxDynamicSharedMemorySize, SMEM);
    cudaFuncSetAttribute((void*)mma_gemm<2>, cudaFuncAttributeMaxDynamicSharedMemorySize, SMEM);
    cudaFuncSetAttribute((void*)mma_gemm<3>, cudaFuncAttributeMaxDynamicSharedMemorySize, SMEM);
    cudaFuncSetAttribute((void*)mma_gemm<4>, cudaFuncAttributeMaxDynamicSharedMemorySize, SMEM);
    cudaFuncSetAttribute((void*)flash_kernel, cudaFuncAttributeMaxDynamicSharedMemorySize, FSMEM);

    const dim3 blk(256);
    const dim3 blkG(128);

    split_kernel<<<(NTOK * DMODEL) / 1024, blk>>>(x, pXs, (long)NTOK * DMODEL, 10);

    for (int l = 0; l < NLAYER; l++) {
        const float* xin  = (l == 0) ? x : pX;
        const float* Wq_l = Wq + (long)l * DMODEL * DMODEL;
        const float* Wk_l = Wk + (long)l * DMODEL * DMODEL;
        const float* Wv_l = Wv + (long)l * DMODEL * DMODEL;
        const float* Wo_l = Wo + (long)l * DMODEL * DMODEL;
        const float* W1_l = W1 + (long)l * DFFN * DMODEL;
        const float* W2_l = W2 + (long)l * DMODEL * DFFN;
        const float* bq_l = bq + (long)l * DMODEL;
        const float* bk_l = bk + (long)l * DMODEL;
        const float* bv_l = bv + (long)l * DMODEL;
        const float* bo_l = bo + (long)l * DMODEL;
        const float* b1_l = b1 + (long)l * DFFN;
        const float* b2_l = b2 + (long)l * DMODEL;
        const float* g1_l = g1 + (long)l * DMODEL;
        const float* be1_l= be1+ (long)l * DMODEL;
        const float* g2_l = g2 + (long)l * DMODEL;
        const float* be2_l= be2+ (long)l * DMODEL;
        const float* rel_l= rel+ (long)l * NREL * HDIM;

        ebar_kernel<<<SS, HDIM>>>(rel_l);

        // Q projection -> split Qs
        mma_gemm<1><<<dim3(16,16,1), blkG, SMEM>>>(
            pXs, 2*DMODEL, 64, DMODEL, Wq_l, DMODEL, bq_l, nullptr,
            pQs, 2*DMODEL, DMODEL, 16);

        // K projection -> K' = K/8 + Ebar -> split Ks
        mma_gemm<3><<<dim3(16,16,1), blkG, SMEM>>>(
            pXs, 2*DMODEL, 64, DMODEL, Wk_l, DMODEL, bk_l, pEB,
            pKs, 2*DMODEL, DMODEL, 16);

        // V projection -> split-transposed VTs directly (fused vtrans)
        mma_gemm<4><<<dim3(16,16,1), blkG, SMEM>>>(
            pXs, 2*DMODEL, 64, DMODEL, Wv_l, DMODEL, bv_l, nullptr,
            pVTs, 0, 0, 16);

        // fused attention: QK' -> softmax -> PV -> split AO
        flash_kernel<<<dim3(BB*NH, SS/128), blk, FSMEM>>>(pQs, pKs, pVTs, pAOs);

        // output projection -> fp32 T1
        mma_gemm<0><<<dim3(16,16,1), blkG, SMEM>>>(
            pAOs, 2*DMODEL, 64, DMODEL, Wo_l, DMODEL, bo_l, nullptr,
            pT1, DMODEL, 0, 16);

        ln_kernel<<<NTOK, blk>>>(xin, pT1, g1_l, be1_l, pX1, pX1s);

        // FFN1 (gelu) -> split Hs
        mma_gemm<2><<<dim3(64,16,1), blkG, SMEM>>>(
            pX1s, 2*DMODEL, 64, DMODEL, W1_l, DMODEL, b1_l, nullptr,
            pHs, 2*DFFN, DFFN, 16);

        // FFN2 -> fp32 T1
        mma_gemm<0><<<dim3(16,16,1), blkG, SMEM>>>(
            pHs, 2*DFFN, 64, DFFN, W2_l, DFFN, b2_l, nullptr,
            pT1, DMODEL, 0, 64);

        ln_kernel<<<NTOK, blk>>>(pX1, pT1, g2_l, be2_l, (l == NLAYER-1) ? out : pX, pXs);
    }
}